// round 1
// baseline (speedup 1.0000x reference)
#include <cuda_runtime.h>
#include <math_constants.h>

// Problem constants (fixed dataset shapes)
#define NMAX 20000
#define EMAX 320000
#define ETOT (EMAX + NMAX)

// ---------------- device scratch (static allocations only) ----------------
__device__ float g_h1[(size_t)NMAX * 128];      // h after input layer / residual for layer1
__device__ float g_h2[(size_t)NMAX * 128];      // h after GAT layer1 (+ln+relu)
__device__ float g_xlxr[(size_t)NMAX * 1024];   // [N][0:512]=xl, [512:1024]=xr
__device__ int   g_cnt[NMAX];
__device__ int   g_rp[NMAX + 1];
__device__ int   g_cur[NMAX];
__device__ int   g_csrc[ETOT];

// ---------------- CSR build ----------------
__global__ void init_cnt_k(int N) {
    int i = blockIdx.x * blockDim.x + threadIdx.x;
    if (i < N) g_cnt[i] = 1;   // self-loop pre-counted
}

__global__ void count_k(const int* __restrict__ dstv, int E) {
    int i = blockIdx.x * blockDim.x + threadIdx.x;
    if (i < E) atomicAdd(&g_cnt[dstv[i]], 1);
}

__global__ void scan_k(int N) {
    __shared__ int sh[1024];
    __shared__ int carry;
    int tid = threadIdx.x;
    if (tid == 0) { carry = 0; g_rp[0] = 0; }
    __syncthreads();
    for (int base = 0; base < N; base += 1024) {
        int i = base + tid;
        int v = (i < N) ? g_cnt[i] : 0;
        sh[tid] = v;
        __syncthreads();
        for (int off = 1; off < 1024; off <<= 1) {
            int t = (tid >= off) ? sh[tid - off] : 0;
            __syncthreads();
            sh[tid] += t;
            __syncthreads();
        }
        if (i < N) {
            int incl = carry + sh[tid];
            g_rp[i + 1] = incl;
            g_cur[i]    = incl - v;   // == row start
        }
        __syncthreads();
        if (tid == 0) carry += sh[1023];
        __syncthreads();
    }
}

__global__ void scatter_k(const int* __restrict__ srcv, const int* __restrict__ dstv,
                          int E, int N) {
    int i = blockIdx.x * blockDim.x + threadIdx.x;
    if (i < E) {
        int d = dstv[i];
        int pos = atomicAdd(&g_cur[d], 1);
        g_csrc[pos] = srcv[i];
    } else if (i < E + N) {
        int n = i - E;
        int pos = atomicAdd(&g_cur[n], 1);
        g_csrc[pos] = n;            // self loop
    }
}

// ---------------- GEMM: out[M, ...] = act(A[M,128] @ W[128,ldw cols] + bias) ----------------
// 128x128 output tile per block, 256 threads, 8x8 micro-tile per thread.
// As stored [r][k] with row stride 132 (pad kills the 2-way tr conflict on a-frag loads).
#define GEMM_SMEM ((128 * 132 + 128 * 128) * 4)

__global__ void gemm_k(const float* __restrict__ A, int M,
                       const float* __restrict__ W, int ldw,
                       const float* __restrict__ bias,
                       float* __restrict__ out, int ldo, int outcol0,
                       int do_relu) {
    extern __shared__ float sm[];
    float* As = sm;                 // [128][132]
    float* Bs = sm + 128 * 132;     // [128][128]  (k-major, same as W)
    int row0 = blockIdx.x * 128;
    int wc0  = blockIdx.y * 128;
    int tid  = threadIdx.x;

    // Load A tile (coalesced: one full 512B row per warp-iter), stores conflict-free.
    #pragma unroll
    for (int it = 0; it < 16; ++it) {
        int idx = it * 256 + tid;
        int r = idx >> 5, kq = idx & 31;
        float4 v = make_float4(0.f, 0.f, 0.f, 0.f);
        if (row0 + r < M) v = *(const float4*)(A + (size_t)(row0 + r) * 128 + kq * 4);
        *(float4*)(As + r * 132 + kq * 4) = v;
    }
    // Load B tile (direct, k-major already).
    #pragma unroll
    for (int it = 0; it < 16; ++it) {
        int idx = it * 256 + tid;
        int k = idx >> 5, cq = idx & 31;
        *(float4*)(Bs + k * 128 + cq * 4) =
            *(const float4*)(W + (size_t)k * ldw + wc0 + cq * 4);
    }
    __syncthreads();

    int tc = tid & 15;              // column group
    int tr = tid >> 4;              // 0..15
    int c0 = tc * 4, c1 = tc * 4 + 64;
    int rb = tr * 4;

    float4 acc0[8], acc1[8];
    #pragma unroll
    for (int j = 0; j < 8; ++j) {
        acc0[j] = make_float4(0.f, 0.f, 0.f, 0.f);
        acc1[j] = make_float4(0.f, 0.f, 0.f, 0.f);
    }

    for (int kb = 0; kb < 128; kb += 4) {
        float4 a[8];
        #pragma unroll
        for (int j = 0; j < 4; ++j) a[j]     = *(float4*)(As + (rb + j) * 132 + kb);
        #pragma unroll
        for (int j = 0; j < 4; ++j) a[4 + j] = *(float4*)(As + (rb + 64 + j) * 132 + kb);
        #pragma unroll
        for (int i = 0; i < 4; ++i) {
            float4 b0 = *(float4*)(Bs + (kb + i) * 128 + c0);
            float4 b1 = *(float4*)(Bs + (kb + i) * 128 + c1);
            #pragma unroll
            for (int j = 0; j < 8; ++j) {
                float av = (i == 0) ? a[j].x : (i == 1) ? a[j].y : (i == 2) ? a[j].z : a[j].w;
                acc0[j].x = fmaf(av, b0.x, acc0[j].x);
                acc0[j].y = fmaf(av, b0.y, acc0[j].y);
                acc0[j].z = fmaf(av, b0.z, acc0[j].z);
                acc0[j].w = fmaf(av, b0.w, acc0[j].w);
                acc1[j].x = fmaf(av, b1.x, acc1[j].x);
                acc1[j].y = fmaf(av, b1.y, acc1[j].y);
                acc1[j].z = fmaf(av, b1.z, acc1[j].z);
                acc1[j].w = fmaf(av, b1.w, acc1[j].w);
            }
        }
    }

    float4 bi0 = *(const float4*)(bias + wc0 + c0);
    float4 bi1 = *(const float4*)(bias + wc0 + c1);
    #pragma unroll
    for (int j = 0; j < 8; ++j) {
        int r = (j < 4) ? (rb + j) : (rb + 64 + (j - 4));
        if (row0 + r >= M) continue;
        float4 o0 = acc0[j], o1 = acc1[j];
        o0.x += bi0.x; o0.y += bi0.y; o0.z += bi0.z; o0.w += bi0.w;
        o1.x += bi1.x; o1.y += bi1.y; o1.z += bi1.z; o1.w += bi1.w;
        if (do_relu) {
            o0.x = fmaxf(o0.x, 0.f); o0.y = fmaxf(o0.y, 0.f);
            o0.z = fmaxf(o0.z, 0.f); o0.w = fmaxf(o0.w, 0.f);
            o1.x = fmaxf(o1.x, 0.f); o1.y = fmaxf(o1.y, 0.f);
            o1.z = fmaxf(o1.z, 0.f); o1.w = fmaxf(o1.w, 0.f);
        }
        float* op = out + (size_t)(row0 + r) * ldo + outcol0 + wc0;
        *(float4*)(op + c0) = o0;
        *(float4*)(op + c1) = o1;
    }
}

// ---------------- GATv2: one warp per destination node, online softmax ----------------
// Fused epilogue: head-mean + bias + residual + LayerNorm + ReLU, then either
// write the [128] hidden row (WRITE_H=1) or project to a scalar head (WRITE_H=0).
template <int WRITE_H>
__global__ void gat_k(const float* __restrict__ xlxr,
                      const float* __restrict__ hres,
                      const float* __restrict__ att,
                      const float* __restrict__ gatb,
                      const float* __restrict__ lng,
                      const float* __restrict__ lnb,
                      const float* __restrict__ headW,
                      const float* __restrict__ headb,
                      float* __restrict__ outh,
                      float* __restrict__ outsc,
                      int N) {
    int n    = (blockIdx.x * blockDim.x + threadIdx.x) >> 5;
    int lane = threadIdx.x & 31;
    if (n >= N) return;

    float4 att4[4], xr4[4];
    const float4* attv = (const float4*)att;
    #pragma unroll
    for (int h = 0; h < 4; ++h) att4[h] = attv[h * 32 + lane];
    const float4* xrv = (const float4*)(xlxr + (size_t)n * 1024 + 512);
    #pragma unroll
    for (int h = 0; h < 4; ++h) xr4[h] = xrv[h * 32 + lane];

    float m[4], d[4];
    float4 acc[4];
    #pragma unroll
    for (int h = 0; h < 4; ++h) {
        m[h] = -CUDART_INF_F; d[h] = 0.f;
        acc[h] = make_float4(0.f, 0.f, 0.f, 0.f);
    }

    int beg = g_rp[n], end = g_rp[n + 1];
    for (int e = beg; e < end; ++e) {
        int src = g_csrc[e];
        const float4* xlv = (const float4*)(xlxr + (size_t)src * 1024);
        float4 xl[4];
        #pragma unroll
        for (int h = 0; h < 4; ++h) xl[h] = xlv[h * 32 + lane];

        float part[4];
        #pragma unroll
        for (int h = 0; h < 4; ++h) {
            float ex = xl[h].x + xr4[h].x; ex = fmaxf(ex, 0.2f * ex);
            float ey = xl[h].y + xr4[h].y; ey = fmaxf(ey, 0.2f * ey);
            float ez = xl[h].z + xr4[h].z; ez = fmaxf(ez, 0.2f * ez);
            float ew = xl[h].w + xr4[h].w; ew = fmaxf(ew, 0.2f * ew);
            part[h] = ex * att4[h].x + ey * att4[h].y + ez * att4[h].z + ew * att4[h].w;
        }
        #pragma unroll
        for (int off = 16; off > 0; off >>= 1) {
            #pragma unroll
            for (int h = 0; h < 4; ++h)
                part[h] += __shfl_xor_sync(0xffffffffu, part[h], off);
        }
        #pragma unroll
        for (int h = 0; h < 4; ++h) {
            float s  = part[h];
            float mn = fmaxf(m[h], s);
            float sc = __expf(m[h] - mn);
            float p  = __expf(s - mn);
            d[h] = d[h] * sc + p;
            acc[h].x = acc[h].x * sc + p * xl[h].x;
            acc[h].y = acc[h].y * sc + p * xl[h].y;
            acc[h].z = acc[h].z * sc + p * xl[h].z;
            acc[h].w = acc[h].w * sc + p * xl[h].w;
            m[h] = mn;
        }
    }

    // head mean + bias + residual
    float id0 = 0.25f / d[0], id1 = 0.25f / d[1], id2 = 0.25f / d[2], id3 = 0.25f / d[3];
    float4 gb = ((const float4*)gatb)[lane];
    float4 hr = ((const float4*)hres)[(size_t)n * 32 + lane];
    float4 v;
    v.x = acc[0].x * id0 + acc[1].x * id1 + acc[2].x * id2 + acc[3].x * id3 + gb.x + hr.x;
    v.y = acc[0].y * id0 + acc[1].y * id1 + acc[2].y * id2 + acc[3].y * id3 + gb.y + hr.y;
    v.z = acc[0].z * id0 + acc[1].z * id1 + acc[2].z * id2 + acc[3].z * id3 + gb.z + hr.z;
    v.w = acc[0].w * id0 + acc[1].w * id1 + acc[2].w * id2 + acc[3].w * id3 + gb.w + hr.w;

    // LayerNorm (128 channels across warp)
    float s1 = v.x + v.y + v.z + v.w;
    float s2 = v.x * v.x + v.y * v.y + v.z * v.z + v.w * v.w;
    #pragma unroll
    for (int off = 16; off > 0; off >>= 1) {
        s1 += __shfl_xor_sync(0xffffffffu, s1, off);
        s2 += __shfl_xor_sync(0xffffffffu, s2, off);
    }
    float mean = s1 * (1.f / 128.f);
    float var  = s2 * (1.f / 128.f) - mean * mean;
    float rstd = rsqrtf(var + 1e-5f);
    float4 g4 = ((const float4*)lng)[lane];
    float4 b4 = ((const float4*)lnb)[lane];
    float4 y;
    y.x = fmaxf((v.x - mean) * rstd * g4.x + b4.x, 0.f);
    y.y = fmaxf((v.y - mean) * rstd * g4.y + b4.y, 0.f);
    y.z = fmaxf((v.z - mean) * rstd * g4.z + b4.z, 0.f);
    y.w = fmaxf((v.w - mean) * rstd * g4.w + b4.w, 0.f);

    if (WRITE_H) {
        ((float4*)outh)[(size_t)n * 32 + lane] = y;
    } else {
        float4 w4 = ((const float4*)headW)[lane];
        float pp = y.x * w4.x + y.y * w4.y + y.z * w4.z + y.w * w4.w;
        #pragma unroll
        for (int off = 16; off > 0; off >>= 1)
            pp += __shfl_xor_sync(0xffffffffu, pp, off);
        if (lane == 0) outsc[n] = pp + headb[0];
    }
}

// ---------------- launch ----------------
extern "C" void kernel_launch(void* const* d_in, const int* in_sizes, int n_in,
                              void* d_out, int out_size) {
    const float* x     = (const float*)d_in[0];
    const int*   ei    = (const int*)d_in[1];
    const float* W_in  = (const float*)d_in[2];
    const float* b_in  = (const float*)d_in[3];
    const float* c1_Wl = (const float*)d_in[4];
    const float* c1_bl = (const float*)d_in[5];
    const float* c1_Wr = (const float*)d_in[6];
    const float* c1_br = (const float*)d_in[7];
    const float* c1_att= (const float*)d_in[8];
    const float* c1_b  = (const float*)d_in[9];
    const float* ln1_g = (const float*)d_in[10];
    const float* ln1_b = (const float*)d_in[11];
    const float* a_Wl  = (const float*)d_in[12];
    const float* a_bl  = (const float*)d_in[13];
    const float* a_Wr  = (const float*)d_in[14];
    const float* a_br  = (const float*)d_in[15];
    const float* a_att = (const float*)d_in[16];
    const float* a_b   = (const float*)d_in[17];
    const float* aln_g = (const float*)d_in[18];
    const float* aln_b = (const float*)d_in[19];
    const float* ah_W  = (const float*)d_in[20];
    const float* ah_b  = (const float*)d_in[21];
    const float* k_Wl  = (const float*)d_in[22];
    const float* k_bl  = (const float*)d_in[23];
    const float* k_Wr  = (const float*)d_in[24];
    const float* k_br  = (const float*)d_in[25];
    const float* k_att = (const float*)d_in[26];
    const float* k_b   = (const float*)d_in[27];
    const float* kln_g = (const float*)d_in[28];
    const float* kln_b = (const float*)d_in[29];
    const float* kh_W  = (const float*)d_in[30];
    const float* kh_b  = (const float*)d_in[31];

    int N = in_sizes[0] / 128;
    int E = in_sizes[1] / 2;
    float* out = (float*)d_out;

    float *h1, *h2, *xlxr;
    cudaGetSymbolAddress((void**)&h1, g_h1);
    cudaGetSymbolAddress((void**)&h2, g_h2);
    cudaGetSymbolAddress((void**)&xlxr, g_xlxr);

    cudaFuncSetAttribute(gemm_k, cudaFuncAttributeMaxDynamicSharedMemorySize, GEMM_SMEM);

    // --- CSR build (dst-major, self-loops included) ---
    init_cnt_k<<<(N + 255) / 256, 256>>>(N);
    count_k<<<(E + 255) / 256, 256>>>(ei + E, E);
    scan_k<<<1, 1024>>>(N);
    scatter_k<<<(E + N + 255) / 256, 256>>>(ei, ei + E, E, N);

    int gm = (N + 127) / 128;          // GEMM row tiles
    int gg = (N + 7) / 8;              // GAT: 8 warps/block

    // --- input layer: h1 = relu(x @ W_in + b_in) ---
    gemm_k<<<dim3(gm, 1), 256, GEMM_SMEM>>>(x, N, W_in, 128, b_in, h1, 128, 0, 1);

    // --- GAT layer 1 ---
    gemm_k<<<dim3(gm, 4), 256, GEMM_SMEM>>>(h1, N, c1_Wl, 512, c1_bl, xlxr, 1024, 0, 0);
    gemm_k<<<dim3(gm, 4), 256, GEMM_SMEM>>>(h1, N, c1_Wr, 512, c1_br, xlxr, 1024, 512, 0);
    gat_k<1><<<gg, 256>>>(xlxr, h1, c1_att, c1_b, ln1_g, ln1_b,
                          (const float*)0, (const float*)0, h2, (float*)0, N);

    // --- actor head ---
    gemm_k<<<dim3(gm, 4), 256, GEMM_SMEM>>>(h2, N, a_Wl, 512, a_bl, xlxr, 1024, 0, 0);
    gemm_k<<<dim3(gm, 4), 256, GEMM_SMEM>>>(h2, N, a_Wr, 512, a_br, xlxr, 1024, 512, 0);
    gat_k<0><<<gg, 256>>>(xlxr, h2, a_att, a_b, aln_g, aln_b,
                          ah_W, ah_b, (float*)0, out, N);

    // --- critic head ---
    gemm_k<<<dim3(gm, 4), 256, GEMM_SMEM>>>(h2, N, k_Wl, 512, k_bl, xlxr, 1024, 0, 0);
    gemm_k<<<dim3(gm, 4), 256, GEMM_SMEM>>>(h2, N, k_Wr, 512, k_br, xlxr, 1024, 512, 0);
    gat_k<0><<<gg, 256>>>(xlxr, h2, k_att, k_b, kln_g, kln_b,
                          kh_W, kh_b, (float*)0, out + N, N);
}

// round 3
// speedup vs baseline: 1.2505x; 1.2505x over previous
#include <cuda_runtime.h>
#include <cuda_bf16.h>
#include <math_constants.h>
#include <cstdint>

// Problem constants (fixed dataset shapes)
#define NMAX 20000
#define EMAX 320000
#define ETOT (EMAX + NMAX)

// ---------------- device scratch (static allocations only) ----------------
__device__ float g_h1[(size_t)NMAX * 128];
__device__ float g_h2[(size_t)NMAX * 128];
__device__ float g_xlxr[(size_t)NMAX * 1024];   // [N][0:512]=xl, [512:1024]=xr
__device__ int   g_cnt[NMAX];
__device__ int   g_rp[NMAX + 1];
__device__ int   g_cur[NMAX];
__device__ int   g_csrc[ETOT];

// transposed bf16 hi/lo weights: rows = 128(W_in) + 6*512 = 3200, each row 128 bf16
#define WT_ROWS 3200
__device__ __nv_bfloat16 g_wthi[(size_t)WT_ROWS * 128];
__device__ __nv_bfloat16 g_wtlo[(size_t)WT_ROWS * 128];

// ---------------- CSR build ----------------
__global__ void init_cnt_k(int N) {
    int i = blockIdx.x * blockDim.x + threadIdx.x;
    if (i < N) g_cnt[i] = 1;
}
__global__ void count_k(const int* __restrict__ dstv, int E) {
    int i = blockIdx.x * blockDim.x + threadIdx.x;
    if (i < E) atomicAdd(&g_cnt[dstv[i]], 1);
}
__global__ void scan_k(int N) {
    __shared__ int sh[1024];
    __shared__ int carry;
    int tid = threadIdx.x;
    if (tid == 0) { carry = 0; g_rp[0] = 0; }
    __syncthreads();
    for (int base = 0; base < N; base += 1024) {
        int i = base + tid;
        int v = (i < N) ? g_cnt[i] : 0;
        sh[tid] = v;
        __syncthreads();
        for (int off = 1; off < 1024; off <<= 1) {
            int t = (tid >= off) ? sh[tid - off] : 0;
            __syncthreads();
            sh[tid] += t;
            __syncthreads();
        }
        if (i < N) {
            int incl = carry + sh[tid];
            g_rp[i + 1] = incl;
            g_cur[i]    = incl - v;
        }
        __syncthreads();
        if (tid == 0) carry += sh[1023];
        __syncthreads();
    }
}
__global__ void scatter_k(const int* __restrict__ srcv, const int* __restrict__ dstv,
                          int E, int N) {
    int i = blockIdx.x * blockDim.x + threadIdx.x;
    if (i < E) {
        int d = dstv[i];
        int pos = atomicAdd(&g_cur[d], 1);
        g_csrc[pos] = srcv[i];
    } else if (i < E + N) {
        int n = i - E;
        int pos = atomicAdd(&g_cur[n], 1);
        g_csrc[pos] = n;
    }
}

// ---------------- weight transpose + fp32 -> bf16 hi/lo ----------------
// W [128, cols] k-major -> Wt [cols, 128] (row = output col, 128 contiguous k)
__global__ void conv_w_k(const float* __restrict__ W, int cols,
                         __nv_bfloat16* __restrict__ hi,
                         __nv_bfloat16* __restrict__ lo) {
    int i = blockIdx.x * blockDim.x + threadIdx.x;
    if (i < 128 * cols) {
        int k = i / cols, n = i % cols;
        float v = W[i];
        __nv_bfloat16 h = __float2bfloat16(v);
        hi[(size_t)n * 128 + k] = h;
        lo[(size_t)n * 128 + k] = __float2bfloat16(v - __bfloat162float(h));
    }
}

// ================= bf16x3 tensor-core GEMM (mma.sync + ldmatrix) =================
// out[row0:row0+128, wc0:wc0+128] = act( A[fp32] @ Wt^T + bias )
// Tiles in smem: [row][k] bf16, padded row stride 272B (17x16B -> conflict-free).
#define TSTRIDE 272
#define TILE_BYTES (128 * TSTRIDE)
#define GMM_SMEM (4 * TILE_BYTES)

__device__ __forceinline__ uint32_t smem_u32(const void* p) {
    uint32_t a;
    asm("{ .reg .u64 t; cvta.to.shared.u64 t, %1; cvt.u32.u64 %0, t; }" : "=r"(a) : "l"(p));
    return a;
}

#define LDMX4(r0, r1, r2, r3, addr) \
    asm volatile("ldmatrix.sync.aligned.m8n8.x4.shared.b16 {%0,%1,%2,%3}, [%4];" \
                 : "=r"(r0), "=r"(r1), "=r"(r2), "=r"(r3) : "r"(addr))

#define MMA_BF16(c, a0, a1, a2, a3, b0, b1) \
    asm volatile("mma.sync.aligned.m16n8k16.row.col.f32.bf16.bf16.f32 " \
                 "{%0,%1,%2,%3}, {%4,%5,%6,%7}, {%8,%9}, {%0,%1,%2,%3};" \
                 : "+f"((c)[0]), "+f"((c)[1]), "+f"((c)[2]), "+f"((c)[3]) \
                 : "r"(a0), "r"(a1), "r"(a2), "r"(a3), "r"(b0), "r"(b1))

__global__ void __launch_bounds__(256, 1)
gemm_mma_k(const float* __restrict__ A, int M,
           const __nv_bfloat16* __restrict__ Bhi, const __nv_bfloat16* __restrict__ Blo,
           const float* __restrict__ bias,
           float* __restrict__ out, int ldo, int outcol0, int do_relu) {
    extern __shared__ char sm[];
    char* sAhi = sm;
    char* sAlo = sm + TILE_BYTES;
    char* sBhi = sm + 2 * TILE_BYTES;
    char* sBlo = sm + 3 * TILE_BYTES;

    int tid = threadIdx.x;
    int row0 = blockIdx.x * 128;
    int wc0  = blockIdx.y * 128;

    // --- A tile: load fp32, split to bf16 hi/lo in registers, store to smem ---
    #pragma unroll
    for (int it = 0; it < 16; ++it) {
        int idx = it * 256 + tid;          // 4096 float4-chunks
        int row = idx >> 5, c = idx & 31;  // c: float4 index within row
        float4 v = make_float4(0.f, 0.f, 0.f, 0.f);
        if (row0 + row < M)
            v = *(const float4*)(A + (size_t)(row0 + row) * 128 + c * 4);
        __nv_bfloat16 hx = __float2bfloat16(v.x);
        __nv_bfloat16 hy = __float2bfloat16(v.y);
        __nv_bfloat16 hz = __float2bfloat16(v.z);
        __nv_bfloat16 hw = __float2bfloat16(v.w);
        __nv_bfloat16 lx = __float2bfloat16(v.x - __bfloat162float(hx));
        __nv_bfloat16 ly = __float2bfloat16(v.y - __bfloat162float(hy));
        __nv_bfloat16 lz = __float2bfloat16(v.z - __bfloat162float(hz));
        __nv_bfloat16 lw = __float2bfloat16(v.w - __bfloat162float(hw));
        uint32_t h01 = (uint32_t)__bfloat16_as_ushort(hx) | ((uint32_t)__bfloat16_as_ushort(hy) << 16);
        uint32_t h23 = (uint32_t)__bfloat16_as_ushort(hz) | ((uint32_t)__bfloat16_as_ushort(hw) << 16);
        uint32_t l01 = (uint32_t)__bfloat16_as_ushort(lx) | ((uint32_t)__bfloat16_as_ushort(ly) << 16);
        uint32_t l23 = (uint32_t)__bfloat16_as_ushort(lz) | ((uint32_t)__bfloat16_as_ushort(lw) << 16);
        *(uint2*)(sAhi + row * TSTRIDE + c * 8) = make_uint2(h01, h23);
        *(uint2*)(sAlo + row * TSTRIDE + c * 8) = make_uint2(l01, l23);
    }
    // --- B tiles: already bf16 [n][128], copy 16B chunks ---
    #pragma unroll
    for (int it = 0; it < 8; ++it) {
        int idx = it * 256 + tid;          // 2048 chunks
        int row = idx >> 4, c = idx & 15;
        *(uint4*)(sBhi + row * TSTRIDE + c * 16) =
            *(const uint4*)((const char*)(Bhi + (size_t)(wc0 + row) * 128) + c * 16);
        *(uint4*)(sBlo + row * TSTRIDE + c * 16) =
            *(const uint4*)((const char*)(Blo + (size_t)(wc0 + row) * 128) + c * 16);
    }
    __syncthreads();

    int wid = tid >> 5;
    int lane = tid & 31;
    int warp_m = wid & 3;          // 4 warps along M (4*32 = 128)
    int warp_n = wid >> 2;         // 2 warps along N (2*64 = 128)

    // ldmatrix per-lane source offsets (common to A and B fragments)
    int gq = lane >> 3, l8 = lane & 7;
    int fr_row = (gq & 1) * 8 + l8;      // row within 16-row block
    int fr_col = (gq >> 1) * 16;         // 16B half within 32B k-step

    uint32_t aoff[2], boff[4];
    #pragma unroll
    for (int mt = 0; mt < 2; ++mt)
        aoff[mt] = (uint32_t)((warp_m * 32 + mt * 16 + fr_row) * TSTRIDE + fr_col);
    #pragma unroll
    for (int nt2 = 0; nt2 < 4; ++nt2)
        boff[nt2] = (uint32_t)((warp_n * 64 + nt2 * 16 + fr_row) * TSTRIDE + fr_col);

    uint32_t uAhi = smem_u32(sAhi), uAlo = smem_u32(sAlo);
    uint32_t uBhi = smem_u32(sBhi), uBlo = smem_u32(sBlo);

    float c[2][8][4];
    #pragma unroll
    for (int mt = 0; mt < 2; ++mt)
        #pragma unroll
        for (int nt = 0; nt < 8; ++nt)
            #pragma unroll
            for (int q = 0; q < 4; ++q) c[mt][nt][q] = 0.f;

    #pragma unroll
    for (int p = 0; p < 3; ++p) {
        uint32_t aB = (p == 2) ? uAlo : uAhi;
        uint32_t bB = (p == 1) ? uBlo : uBhi;
        #pragma unroll
        for (int kk = 0; kk < 8; ++kk) {
            uint32_t a[2][4];
            #pragma unroll
            for (int mt = 0; mt < 2; ++mt)
                LDMX4(a[mt][0], a[mt][1], a[mt][2], a[mt][3], aB + aoff[mt] + kk * 32);
            uint32_t b[4][4];
            #pragma unroll
            for (int nt2 = 0; nt2 < 4; ++nt2)
                LDMX4(b[nt2][0], b[nt2][1], b[nt2][2], b[nt2][3], bB + boff[nt2] + kk * 32);
            #pragma unroll
            for (int mt = 0; mt < 2; ++mt)
                #pragma unroll
                for (int nt = 0; nt < 8; ++nt) {
                    int nt2 = nt >> 1, odd = nt & 1;
                    MMA_BF16(c[mt][nt], a[mt][0], a[mt][1], a[mt][2], a[mt][3],
                             b[nt2][odd], b[nt2][2 + odd]);
                }
        }
    }

    // --- epilogue: bias (+relu), direct global write ---
    int qr = lane >> 2;            // 0..7
    int qc = (lane & 3) * 2;       // 0,2,4,6
    #pragma unroll
    for (int mt = 0; mt < 2; ++mt) {
        int r_lo = row0 + warp_m * 32 + mt * 16 + qr;
        #pragma unroll
        for (int nt = 0; nt < 8; ++nt) {
            int col = wc0 + warp_n * 64 + nt * 8 + qc;
            float2 bv = *(const float2*)(bias + col);
            float2 v0 = make_float2(c[mt][nt][0] + bv.x, c[mt][nt][1] + bv.y);
            float2 v1 = make_float2(c[mt][nt][2] + bv.x, c[mt][nt][3] + bv.y);
            if (do_relu) {
                v0.x = fmaxf(v0.x, 0.f); v0.y = fmaxf(v0.y, 0.f);
                v1.x = fmaxf(v1.x, 0.f); v1.y = fmaxf(v1.y, 0.f);
            }
            if (r_lo < M)
                *(float2*)(out + (size_t)r_lo * ldo + outcol0 + col) = v0;
            if (r_lo + 8 < M)
                *(float2*)(out + (size_t)(r_lo + 8) * ldo + outcol0 + col) = v1;
        }
    }
}

// ---------------- GATv2: one warp per destination node, online softmax ----------------
template <int WRITE_H>
__global__ void gat_k(const float* __restrict__ xlxr,
                      const float* __restrict__ hres,
                      const float* __restrict__ att,
                      const float* __restrict__ gatb,
                      const float* __restrict__ lng,
                      const float* __restrict__ lnb,
                      const float* __restrict__ headW,
                      const float* __restrict__ headb,
                      float* __restrict__ outh,
                      float* __restrict__ outsc,
                      int N) {
    int n    = (blockIdx.x * blockDim.x + threadIdx.x) >> 5;
    int lane = threadIdx.x & 31;
    if (n >= N) return;

    float4 att4[4], xr4[4];
    const float4* attv = (const float4*)att;
    #pragma unroll
    for (int h = 0; h < 4; ++h) att4[h] = attv[h * 32 + lane];
    const float4* xrv = (const float4*)(xlxr + (size_t)n * 1024 + 512);
    #pragma unroll
    for (int h = 0; h < 4; ++h) xr4[h] = xrv[h * 32 + lane];

    float m[4], d[4];
    float4 acc[4];
    #pragma unroll
    for (int h = 0; h < 4; ++h) {
        m[h] = -CUDART_INF_F; d[h] = 0.f;
        acc[h] = make_float4(0.f, 0.f, 0.f, 0.f);
    }

    int beg = g_rp[n], end = g_rp[n + 1];
    for (int e = beg; e < end; ++e) {
        int src = g_csrc[e];
        const float4* xlv = (const float4*)(xlxr + (size_t)src * 1024);
        float4 xl[4];
        #pragma unroll
        for (int h = 0; h < 4; ++h) xl[h] = xlv[h * 32 + lane];

        float part[4];
        #pragma unroll
        for (int h = 0; h < 4; ++h) {
            float ex = xl[h].x + xr4[h].x; ex = fmaxf(ex, 0.2f * ex);
            float ey = xl[h].y + xr4[h].y; ey = fmaxf(ey, 0.2f * ey);
            float ez = xl[h].z + xr4[h].z; ez = fmaxf(ez, 0.2f * ez);
            float ew = xl[h].w + xr4[h].w; ew = fmaxf(ew, 0.2f * ew);
            part[h] = ex * att4[h].x + ey * att4[h].y + ez * att4[h].z + ew * att4[h].w;
        }
        #pragma unroll
        for (int off = 16; off > 0; off >>= 1) {
            #pragma unroll
            for (int h = 0; h < 4; ++h)
                part[h] += __shfl_xor_sync(0xffffffffu, part[h], off);
        }
        #pragma unroll
        for (int h = 0; h < 4; ++h) {
            float s  = part[h];
            float mn = fmaxf(m[h], s);
            float sc = __expf(m[h] - mn);
            float p  = __expf(s - mn);
            d[h] = d[h] * sc + p;
            acc[h].x = acc[h].x * sc + p * xl[h].x;
            acc[h].y = acc[h].y * sc + p * xl[h].y;
            acc[h].z = acc[h].z * sc + p * xl[h].z;
            acc[h].w = acc[h].w * sc + p * xl[h].w;
            m[h] = mn;
        }
    }

    float id0 = 0.25f / d[0], id1 = 0.25f / d[1], id2 = 0.25f / d[2], id3 = 0.25f / d[3];
    float4 gb = ((const float4*)gatb)[lane];
    float4 hr = ((const float4*)hres)[(size_t)n * 32 + lane];
    float4 v;
    v.x = acc[0].x * id0 + acc[1].x * id1 + acc[2].x * id2 + acc[3].x * id3 + gb.x + hr.x;
    v.y = acc[0].y * id0 + acc[1].y * id1 + acc[2].y * id2 + acc[3].y * id3 + gb.y + hr.y;
    v.z = acc[0].z * id0 + acc[1].z * id1 + acc[2].z * id2 + acc[3].z * id3 + gb.z + hr.z;
    v.w = acc[0].w * id0 + acc[1].w * id1 + acc[2].w * id2 + acc[3].w * id3 + gb.w + hr.w;

    float s1 = v.x + v.y + v.z + v.w;
    float s2 = v.x * v.x + v.y * v.y + v.z * v.z + v.w * v.w;
    #pragma unroll
    for (int off = 16; off > 0; off >>= 1) {
        s1 += __shfl_xor_sync(0xffffffffu, s1, off);
        s2 += __shfl_xor_sync(0xffffffffu, s2, off);
    }
    float mean = s1 * (1.f / 128.f);
    float var  = s2 * (1.f / 128.f) - mean * mean;
    float rstd = rsqrtf(var + 1e-5f);
    float4 g4 = ((const float4*)lng)[lane];
    float4 b4 = ((const float4*)lnb)[lane];
    float4 y;
    y.x = fmaxf((v.x - mean) * rstd * g4.x + b4.x, 0.f);
    y.y = fmaxf((v.y - mean) * rstd * g4.y + b4.y, 0.f);
    y.z = fmaxf((v.z - mean) * rstd * g4.z + b4.z, 0.f);
    y.w = fmaxf((v.w - mean) * rstd * g4.w + b4.w, 0.f);

    if (WRITE_H) {
        ((float4*)outh)[(size_t)n * 32 + lane] = y;
    } else {
        float4 w4 = ((const float4*)headW)[lane];
        float pp = y.x * w4.x + y.y * w4.y + y.z * w4.z + y.w * w4.w;
        #pragma unroll
        for (int off = 16; off > 0; off >>= 1)
            pp += __shfl_xor_sync(0xffffffffu, pp, off);
        if (lane == 0) outsc[n] = pp + headb[0];
    }
}

// ---------------- launch ----------------
extern "C" void kernel_launch(void* const* d_in, const int* in_sizes, int n_in,
                              void* d_out, int out_size) {
    const float* x     = (const float*)d_in[0];
    const int*   ei    = (const int*)d_in[1];
    const float* W_in  = (const float*)d_in[2];
    const float* b_in  = (const float*)d_in[3];
    const float* c1_Wl = (const float*)d_in[4];
    const float* c1_bl = (const float*)d_in[5];
    const float* c1_Wr = (const float*)d_in[6];
    const float* c1_br = (const float*)d_in[7];
    const float* c1_att= (const float*)d_in[8];
    const float* c1_b  = (const float*)d_in[9];
    const float* ln1_g = (const float*)d_in[10];
    const float* ln1_b = (const float*)d_in[11];
    const float* a_Wl  = (const float*)d_in[12];
    const float* a_bl  = (const float*)d_in[13];
    const float* a_Wr  = (const float*)d_in[14];
    const float* a_br  = (const float*)d_in[15];
    const float* a_att = (const float*)d_in[16];
    const float* a_b   = (const float*)d_in[17];
    const float* aln_g = (const float*)d_in[18];
    const float* aln_b = (const float*)d_in[19];
    const float* ah_W  = (const float*)d_in[20];
    const float* ah_b  = (const float*)d_in[21];
    const float* k_Wl  = (const float*)d_in[22];
    const float* k_bl  = (const float*)d_in[23];
    const float* k_Wr  = (const float*)d_in[24];
    const float* k_br  = (const float*)d_in[25];
    const float* k_att = (const float*)d_in[26];
    const float* k_b   = (const float*)d_in[27];
    const float* kln_g = (const float*)d_in[28];
    const float* kln_b = (const float*)d_in[29];
    const float* kh_W  = (const float*)d_in[30];
    const float* kh_b  = (const float*)d_in[31];

    int N = in_sizes[0] / 128;
    int E = in_sizes[1] / 2;
    float* out = (float*)d_out;

    float *h1, *h2, *xlxr;
    __nv_bfloat16 *wthi, *wtlo;
    cudaGetSymbolAddress((void**)&h1, g_h1);
    cudaGetSymbolAddress((void**)&h2, g_h2);
    cudaGetSymbolAddress((void**)&xlxr, g_xlxr);
    cudaGetSymbolAddress((void**)&wthi, g_wthi);
    cudaGetSymbolAddress((void**)&wtlo, g_wtlo);

    cudaFuncSetAttribute(gemm_mma_k, cudaFuncAttributeMaxDynamicSharedMemorySize, GMM_SMEM);

    // --- CSR build (dst-major, self-loops included) ---
    init_cnt_k<<<(N + 255) / 256, 256>>>(N);
    count_k<<<(E + 255) / 256, 256>>>(ei + E, E);
    scan_k<<<1, 1024>>>(N);
    scatter_k<<<(E + N + 255) / 256, 256>>>(ei, ei + E, E, N);

    // --- weight transpose + hi/lo convert (row offsets into g_wt) ---
    int gw128 = (128 * 128 + 255) / 256;
    int gw512 = (128 * 512 + 255) / 256;
    conv_w_k<<<gw128, 256>>>(W_in,  128, wthi + (size_t)0 * 128,    wtlo + (size_t)0 * 128);
    conv_w_k<<<gw512, 256>>>(c1_Wl, 512, wthi + (size_t)128 * 128,  wtlo + (size_t)128 * 128);
    conv_w_k<<<gw512, 256>>>(c1_Wr, 512, wthi + (size_t)640 * 128,  wtlo + (size_t)640 * 128);
    conv_w_k<<<gw512, 256>>>(a_Wl,  512, wthi + (size_t)1152 * 128, wtlo + (size_t)1152 * 128);
    conv_w_k<<<gw512, 256>>>(a_Wr,  512, wthi + (size_t)1664 * 128, wtlo + (size_t)1664 * 128);
    conv_w_k<<<gw512, 256>>>(k_Wl,  512, wthi + (size_t)2176 * 128, wtlo + (size_t)2176 * 128);
    conv_w_k<<<gw512, 256>>>(k_Wr,  512, wthi + (size_t)2688 * 128, wtlo + (size_t)2688 * 128);

    int gm = (N + 127) / 128;
    int gg = (N + 7) / 8;

    // --- input layer: h1 = relu(x @ W_in + b_in) ---
    gemm_mma_k<<<dim3(gm, 1), 256, GMM_SMEM>>>(x, N,
        wthi + (size_t)0 * 128, wtlo + (size_t)0 * 128, b_in, h1, 128, 0, 1);

    // --- GAT layer 1 ---
    gemm_mma_k<<<dim3(gm, 4), 256, GMM_SMEM>>>(h1, N,
        wthi + (size_t)128 * 128, wtlo + (size_t)128 * 128, c1_bl, xlxr, 1024, 0, 0);
    gemm_mma_k<<<dim3(gm, 4), 256, GMM_SMEM>>>(h1, N,
        wthi + (size_t)640 * 128, wtlo + (size_t)640 * 128, c1_br, xlxr, 1024, 512, 0);
    gat_k<1><<<gg, 256>>>(xlxr, h1, c1_att, c1_b, ln1_g, ln1_b,
                          (const float*)0, (const float*)0, h2, (float*)0, N);

    // --- actor head ---
    gemm_mma_k<<<dim3(gm, 4), 256, GMM_SMEM>>>(h2, N,
        wthi + (size_t)1152 * 128, wtlo + (size_t)1152 * 128, a_bl, xlxr, 1024, 0, 0);
    gemm_mma_k<<<dim3(gm, 4), 256, GMM_SMEM>>>(h2, N,
        wthi + (size_t)1664 * 128, wtlo + (size_t)1664 * 128, a_br, xlxr, 1024, 512, 0);
    gat_k<0><<<gg, 256>>>(xlxr, h2, a_att, a_b, aln_g, aln_b,
                          ah_W, ah_b, (float*)0, out, N);

    // --- critic head ---
    gemm_mma_k<<<dim3(gm, 4), 256, GMM_SMEM>>>(h2, N,
        wthi + (size_t)2176 * 128, wtlo + (size_t)2176 * 128, k_bl, xlxr, 1024, 0, 0);
    gemm_mma_k<<<dim3(gm, 4), 256, GMM_SMEM>>>(h2, N,
        wthi + (size_t)2688 * 128, wtlo + (size_t)2688 * 128, k_br, xlxr, 1024, 512, 0);
    gat_k<0><<<gg, 256>>>(xlxr, h2, k_att, k_b, kln_g, kln_b,
                          kh_W, kh_b, (float*)0, out + N, N);
}

// round 4
// speedup vs baseline: 1.2616x; 1.0089x over previous
#include <cuda_runtime.h>
#include <cuda_bf16.h>
#include <math_constants.h>
#include <cstdint>

// Problem constants (fixed dataset shapes)
#define NMAX 20000
#define EMAX 320000
#define ETOT (EMAX + NMAX)

// ---------------- device scratch (static allocations only) ----------------
__device__ float g_h1[(size_t)NMAX * 128];
__device__ float g_h2[(size_t)NMAX * 128];
__device__ float g_xlxr[(size_t)NMAX * 1024];   // [N][0:512]=xl, [512:1024]=xr
__device__ int   g_cnt[NMAX];
__device__ int   g_rp[NMAX + 1];
__device__ int   g_cur[NMAX];
__device__ int   g_csrc[ETOT];

// transposed bf16 hi/lo weights: rows = 128(W_in) + 6*512 = 3200, each row 128 bf16
#define WT_ROWS 3200
__device__ __nv_bfloat16 g_wthi[(size_t)WT_ROWS * 128];
__device__ __nv_bfloat16 g_wtlo[(size_t)WT_ROWS * 128];

// ---------------- CSR build ----------------
__global__ void init_cnt_k(int N) {
    int i = blockIdx.x * blockDim.x + threadIdx.x;
    if (i < N) g_cnt[i] = 1;
}
__global__ void count_k(const int* __restrict__ dstv, int E) {
    int i = blockIdx.x * blockDim.x + threadIdx.x;
    if (i < E) atomicAdd(&g_cnt[dstv[i]], 1);
}
// single-block 1024-thread prefix scan over g_cnt -> g_rp (inclusive at i+1), g_cur = row start
__global__ void scan2_k(int N) {
    __shared__ int wsum[32];
    int tid = threadIdx.x;
    int lane = tid & 31, wid = tid >> 5;
    int per = (N + 1023) >> 10;
    int start = tid * per;
    int s = 0;
    for (int i = 0; i < per; ++i) {
        int idx = start + i;
        if (idx < N) s += g_cnt[idx];
    }
    int v = s;
    #pragma unroll
    for (int off = 1; off < 32; off <<= 1) {
        int t = __shfl_up_sync(0xffffffffu, v, off);
        if (lane >= off) v += t;
    }
    if (lane == 31) wsum[wid] = v;
    __syncthreads();
    if (wid == 0) {
        int w = wsum[lane];
        #pragma unroll
        for (int off = 1; off < 32; off <<= 1) {
            int t = __shfl_up_sync(0xffffffffu, w, off);
            if (lane >= off) w += t;
        }
        wsum[lane] = w;
    }
    __syncthreads();
    int excl = v - s + (wid ? wsum[wid - 1] : 0);
    int run = excl;
    for (int i = 0; i < per; ++i) {
        int idx = start + i;
        if (idx < N) {
            int c = g_cnt[idx];
            g_cur[idx] = run;
            run += c;
            g_rp[idx + 1] = run;
        }
    }
    if (tid == 0) g_rp[0] = 0;
}
__global__ void scatter_k(const int* __restrict__ srcv, const int* __restrict__ dstv,
                          int E, int N) {
    int i = blockIdx.x * blockDim.x + threadIdx.x;
    if (i < E) {
        int d = dstv[i];
        int pos = atomicAdd(&g_cur[d], 1);
        g_csrc[pos] = srcv[i];
    } else if (i < E + N) {
        int n = i - E;
        int pos = atomicAdd(&g_cur[n], 1);
        g_csrc[pos] = n;
    }
}

// ---------------- all weight transposes + fp32 -> bf16 hi/lo in ONE launch ----------------
// seg0: W_in (cols=128, 16384 elems, rows [0,128))
// seg s=1..6: 512-col weights, 65536 elems each, rows 128 + (s-1)*512
__global__ void conv_all_k(const float* __restrict__ w0, const float* __restrict__ w1,
                           const float* __restrict__ w2, const float* __restrict__ w3,
                           const float* __restrict__ w4, const float* __restrict__ w5,
                           const float* __restrict__ w6,
                           __nv_bfloat16* __restrict__ hi, __nv_bfloat16* __restrict__ lo) {
    int i = blockIdx.x * blockDim.x + threadIdx.x;
    if (i >= 16384 + 6 * 65536) return;
    const float* W; int cols, rowoff, li;
    if (i < 16384) { W = w0; cols = 128; rowoff = 0; li = i; }
    else {
        int s = (i - 16384) >> 16;
        li = (i - 16384) & 65535;
        W = (s == 0) ? w1 : (s == 1) ? w2 : (s == 2) ? w3 : (s == 3) ? w4 : (s == 4) ? w5 : w6;
        cols = 512; rowoff = 128 + s * 512;
    }
    int k = li / cols, n = li % cols;
    float v = W[li];
    __nv_bfloat16 h = __float2bfloat16(v);
    hi[(size_t)(rowoff + n) * 128 + k] = h;
    lo[(size_t)(rowoff + n) * 128 + k] = __float2bfloat16(v - __bfloat162float(h));
}

// ================= bf16x3 tensor-core GEMM (mma.sync + ldmatrix) =================
#define TSTRIDE 272
#define TILE_BYTES (128 * TSTRIDE)
#define GMM_SMEM (4 * TILE_BYTES)

__device__ __forceinline__ uint32_t smem_u32(const void* p) {
    uint32_t a;
    asm("{ .reg .u64 t; cvta.to.shared.u64 t, %1; cvt.u32.u64 %0, t; }" : "=r"(a) : "l"(p));
    return a;
}

#define LDMX4(r0, r1, r2, r3, addr) \
    asm volatile("ldmatrix.sync.aligned.m8n8.x4.shared.b16 {%0,%1,%2,%3}, [%4];" \
                 : "=r"(r0), "=r"(r1), "=r"(r2), "=r"(r3) : "r"(addr))

#define MMA_BF16(c, a0, a1, a2, a3, b0, b1) \
    asm volatile("mma.sync.aligned.m16n8k16.row.col.f32.bf16.bf16.f32 " \
                 "{%0,%1,%2,%3}, {%4,%5,%6,%7}, {%8,%9}, {%0,%1,%2,%3};" \
                 : "+f"((c)[0]), "+f"((c)[1]), "+f"((c)[2]), "+f"((c)[3]) \
                 : "r"(a0), "r"(a1), "r"(a2), "r"(a3), "r"(b0), "r"(b1))

__global__ void __launch_bounds__(256, 1)
gemm_mma_k(const float* __restrict__ A, int M,
           const __nv_bfloat16* __restrict__ Bhi, const __nv_bfloat16* __restrict__ Blo,
           const float* __restrict__ bias,
           float* __restrict__ out, int ldo, int outcol0, int do_relu) {
    extern __shared__ char sm[];
    char* sAhi = sm;
    char* sAlo = sm + TILE_BYTES;
    char* sBhi = sm + 2 * TILE_BYTES;
    char* sBlo = sm + 3 * TILE_BYTES;

    int tid = threadIdx.x;
    int row0 = blockIdx.x * 128;
    int wc0  = blockIdx.y * 128;

    #pragma unroll
    for (int it = 0; it < 16; ++it) {
        int idx = it * 256 + tid;
        int row = idx >> 5, c = idx & 31;
        float4 v = make_float4(0.f, 0.f, 0.f, 0.f);
        if (row0 + row < M)
            v = *(const float4*)(A + (size_t)(row0 + row) * 128 + c * 4);
        __nv_bfloat16 hx = __float2bfloat16(v.x);
        __nv_bfloat16 hy = __float2bfloat16(v.y);
        __nv_bfloat16 hz = __float2bfloat16(v.z);
        __nv_bfloat16 hw = __float2bfloat16(v.w);
        __nv_bfloat16 lx = __float2bfloat16(v.x - __bfloat162float(hx));
        __nv_bfloat16 ly = __float2bfloat16(v.y - __bfloat162float(hy));
        __nv_bfloat16 lz = __float2bfloat16(v.z - __bfloat162float(hz));
        __nv_bfloat16 lw = __float2bfloat16(v.w - __bfloat162float(hw));
        uint32_t h01 = (uint32_t)__bfloat16_as_ushort(hx) | ((uint32_t)__bfloat16_as_ushort(hy) << 16);
        uint32_t h23 = (uint32_t)__bfloat16_as_ushort(hz) | ((uint32_t)__bfloat16_as_ushort(hw) << 16);
        uint32_t l01 = (uint32_t)__bfloat16_as_ushort(lx) | ((uint32_t)__bfloat16_as_ushort(ly) << 16);
        uint32_t l23 = (uint32_t)__bfloat16_as_ushort(lz) | ((uint32_t)__bfloat16_as_ushort(lw) << 16);
        *(uint2*)(sAhi + row * TSTRIDE + c * 8) = make_uint2(h01, h23);
        *(uint2*)(sAlo + row * TSTRIDE + c * 8) = make_uint2(l01, l23);
    }
    #pragma unroll
    for (int it = 0; it < 8; ++it) {
        int idx = it * 256 + tid;
        int row = idx >> 4, c = idx & 15;
        *(uint4*)(sBhi + row * TSTRIDE + c * 16) =
            *(const uint4*)((const char*)(Bhi + (size_t)(wc0 + row) * 128) + c * 16);
        *(uint4*)(sBlo + row * TSTRIDE + c * 16) =
            *(const uint4*)((const char*)(Blo + (size_t)(wc0 + row) * 128) + c * 16);
    }
    __syncthreads();

    int wid = tid >> 5;
    int lane = tid & 31;
    int warp_m = wid & 3;
    int warp_n = wid >> 2;

    int gq = lane >> 3, l8 = lane & 7;
    int fr_row = (gq & 1) * 8 + l8;
    int fr_col = (gq >> 1) * 16;

    uint32_t aoff[2], boff[4];
    #pragma unroll
    for (int mt = 0; mt < 2; ++mt)
        aoff[mt] = (uint32_t)((warp_m * 32 + mt * 16 + fr_row) * TSTRIDE + fr_col);
    #pragma unroll
    for (int nt2 = 0; nt2 < 4; ++nt2)
        boff[nt2] = (uint32_t)((warp_n * 64 + nt2 * 16 + fr_row) * TSTRIDE + fr_col);

    uint32_t uAhi = smem_u32(sAhi), uAlo = smem_u32(sAlo);
    uint32_t uBhi = smem_u32(sBhi), uBlo = smem_u32(sBlo);

    float c[2][8][4];
    #pragma unroll
    for (int mt = 0; mt < 2; ++mt)
        #pragma unroll
        for (int nt = 0; nt < 8; ++nt)
            #pragma unroll
            for (int q = 0; q < 4; ++q) c[mt][nt][q] = 0.f;

    #pragma unroll
    for (int p = 0; p < 3; ++p) {
        uint32_t aB = (p == 2) ? uAlo : uAhi;
        uint32_t bB = (p == 1) ? uBlo : uBhi;
        #pragma unroll
        for (int kk = 0; kk < 8; ++kk) {
            uint32_t a[2][4];
            #pragma unroll
            for (int mt = 0; mt < 2; ++mt)
                LDMX4(a[mt][0], a[mt][1], a[mt][2], a[mt][3], aB + aoff[mt] + kk * 32);
            uint32_t b[4][4];
            #pragma unroll
            for (int nt2 = 0; nt2 < 4; ++nt2)
                LDMX4(b[nt2][0], b[nt2][1], b[nt2][2], b[nt2][3], bB + boff[nt2] + kk * 32);
            #pragma unroll
            for (int mt = 0; mt < 2; ++mt)
                #pragma unroll
                for (int nt = 0; nt < 8; ++nt) {
                    int nt2 = nt >> 1, odd = nt & 1;
                    MMA_BF16(c[mt][nt], a[mt][0], a[mt][1], a[mt][2], a[mt][3],
                             b[nt2][odd], b[nt2][2 + odd]);
                }
        }
    }

    int qr = lane >> 2;
    int qc = (lane & 3) * 2;
    #pragma unroll
    for (int mt = 0; mt < 2; ++mt) {
        int r_lo = row0 + warp_m * 32 + mt * 16 + qr;
        #pragma unroll
        for (int nt = 0; nt < 8; ++nt) {
            int col = wc0 + warp_n * 64 + nt * 8 + qc;
            float2 bv = *(const float2*)(bias + col);
            float2 v0 = make_float2(c[mt][nt][0] + bv.x, c[mt][nt][1] + bv.y);
            float2 v1 = make_float2(c[mt][nt][2] + bv.x, c[mt][nt][3] + bv.y);
            if (do_relu) {
                v0.x = fmaxf(v0.x, 0.f); v0.y = fmaxf(v0.y, 0.f);
                v1.x = fmaxf(v1.x, 0.f); v1.y = fmaxf(v1.y, 0.f);
            }
            if (r_lo < M)
                *(float2*)(out + (size_t)r_lo * ldo + outcol0 + col) = v0;
            if (r_lo + 8 < M)
                *(float2*)(out + (size_t)(r_lo + 8) * ldo + outcol0 + col) = v1;
        }
    }
}

// ================= GATv2 v2: warp/node, 8-lane head groups, 2-edge unroll =================
#define LRD(t, x4, r4, a4) do {                                        \
    float ex = (x4).x + (r4).x; ex = fmaxf(ex, 0.2f * ex); t = fmaf(ex, (a4).x, t); \
    float ey = (x4).y + (r4).y; ey = fmaxf(ey, 0.2f * ey); t = fmaf(ey, (a4).y, t); \
    float ez = (x4).z + (r4).z; ez = fmaxf(ez, 0.2f * ez); t = fmaf(ez, (a4).z, t); \
    float ew = (x4).w + (r4).w; ew = fmaxf(ew, 0.2f * ew); t = fmaf(ew, (a4).w, t); \
} while (0)

template <int WRITE_H>
__global__ void __launch_bounds__(256)
gat2_k(const float* __restrict__ xlxr,
       const float* __restrict__ hres,
       const float* __restrict__ att,
       const float* __restrict__ gatb,
       const float* __restrict__ lng,
       const float* __restrict__ lnb,
       const float* __restrict__ headW,
       const float* __restrict__ headb,
       float* __restrict__ outh,
       float* __restrict__ outsc,
       int N) {
    int n    = (blockIdx.x * blockDim.x + threadIdx.x) >> 5;
    int lane = threadIdx.x & 31;
    if (n >= N) return;
    int g  = lane >> 3;          // head (group of 8 lanes)
    int l8 = lane & 7;           // channel block within head
    int cb = g * 32 + l8 * 4;    // float4 index of channel base within 512

    float4 atv[4], xrv[4];
    const float4* ap = (const float4*)att + cb;
    const float4* xp = (const float4*)(xlxr + (size_t)n * 1024 + 512) + cb;
    #pragma unroll
    for (int j = 0; j < 4; ++j) { atv[j] = ap[j]; xrv[j] = xp[j]; }

    float m = -CUDART_INF_F, d = 0.f;
    float4 acc[4];
    #pragma unroll
    for (int j = 0; j < 4; ++j) acc[j] = make_float4(0.f, 0.f, 0.f, 0.f);

    int e = g_rp[n], end = g_rp[n + 1];
    for (; e + 2 <= end; e += 2) {
        int s0 = g_csrc[e];
        int s1 = g_csrc[e + 1];
        const float4* q0 = (const float4*)(xlxr + (size_t)s0 * 1024) + cb;
        const float4* q1 = (const float4*)(xlxr + (size_t)s1 * 1024) + cb;
        float4 x0[4], x1[4];
        #pragma unroll
        for (int j = 0; j < 4; ++j) x0[j] = q0[j];
        #pragma unroll
        for (int j = 0; j < 4; ++j) x1[j] = q1[j];

        float t0 = 0.f, t1 = 0.f;
        #pragma unroll
        for (int j = 0; j < 4; ++j) { LRD(t0, x0[j], xrv[j], atv[j]); LRD(t1, x1[j], xrv[j], atv[j]); }
        // 8-lane reduction for both scores (interleaved)
        t0 += __shfl_xor_sync(0xffffffffu, t0, 1);
        t1 += __shfl_xor_sync(0xffffffffu, t1, 1);
        t0 += __shfl_xor_sync(0xffffffffu, t0, 2);
        t1 += __shfl_xor_sync(0xffffffffu, t1, 2);
        t0 += __shfl_xor_sync(0xffffffffu, t0, 4);
        t1 += __shfl_xor_sync(0xffffffffu, t1, 4);

        float mn = fmaxf(m, fmaxf(t0, t1));
        float sc = __expf(m - mn);
        float p0 = __expf(t0 - mn);
        float p1 = __expf(t1 - mn);
        d = fmaf(d, sc, p0 + p1);
        #pragma unroll
        for (int j = 0; j < 4; ++j) {
            acc[j].x = fmaf(acc[j].x, sc, fmaf(p0, x0[j].x, p1 * x1[j].x));
            acc[j].y = fmaf(acc[j].y, sc, fmaf(p0, x0[j].y, p1 * x1[j].y));
            acc[j].z = fmaf(acc[j].z, sc, fmaf(p0, x0[j].z, p1 * x1[j].z));
            acc[j].w = fmaf(acc[j].w, sc, fmaf(p0, x0[j].w, p1 * x1[j].w));
        }
        m = mn;
    }
    if (e < end) {
        int s0 = g_csrc[e];
        const float4* q0 = (const float4*)(xlxr + (size_t)s0 * 1024) + cb;
        float4 x0[4];
        #pragma unroll
        for (int j = 0; j < 4; ++j) x0[j] = q0[j];
        float t0 = 0.f;
        #pragma unroll
        for (int j = 0; j < 4; ++j) LRD(t0, x0[j], xrv[j], atv[j]);
        t0 += __shfl_xor_sync(0xffffffffu, t0, 1);
        t0 += __shfl_xor_sync(0xffffffffu, t0, 2);
        t0 += __shfl_xor_sync(0xffffffffu, t0, 4);
        float mn = fmaxf(m, t0);
        float sc = __expf(m - mn);
        float p0 = __expf(t0 - mn);
        d = fmaf(d, sc, p0);
        #pragma unroll
        for (int j = 0; j < 4; ++j) {
            acc[j].x = fmaf(acc[j].x, sc, p0 * x0[j].x);
            acc[j].y = fmaf(acc[j].y, sc, p0 * x0[j].y);
            acc[j].z = fmaf(acc[j].z, sc, p0 * x0[j].z);
            acc[j].w = fmaf(acc[j].w, sc, p0 * x0[j].w);
        }
        m = mn;
    }

    // merge heads: v_c = 0.25 * sum_g acc_g[c] / d_g  (sum across groups via xor 8,16)
    float inv = 0.25f / d;
    float* a = (float*)acc;
    #pragma unroll
    for (int i = 0; i < 16; ++i) {
        float v = a[i] * inv;
        v += __shfl_xor_sync(0xffffffffu, v, 8);
        v += __shfl_xor_sync(0xffffffffu, v, 16);
        a[i] = v;
    }

    // epilogue: channels c0 = l8*16 (+0..15); replicated across groups
    int fb = l8 * 4;   // float4 index within 128-channel row
    const float4* gbp = (const float4*)gatb + fb;
    const float4* hrp = (const float4*)(hres + (size_t)n * 128) + fb;
    float4 v4[4];
    float s1 = 0.f, s2 = 0.f;
    #pragma unroll
    for (int j = 0; j < 4; ++j) {
        float4 gb = gbp[j], hr = hrp[j];
        v4[j].x = acc[j].x + gb.x + hr.x;
        v4[j].y = acc[j].y + gb.y + hr.y;
        v4[j].z = acc[j].z + gb.z + hr.z;
        v4[j].w = acc[j].w + gb.w + hr.w;
        s1 += v4[j].x + v4[j].y + v4[j].z + v4[j].w;
        s2 += v4[j].x * v4[j].x + v4[j].y * v4[j].y + v4[j].z * v4[j].z + v4[j].w * v4[j].w;
    }
    s1 += __shfl_xor_sync(0xffffffffu, s1, 1);
    s2 += __shfl_xor_sync(0xffffffffu, s2, 1);
    s1 += __shfl_xor_sync(0xffffffffu, s1, 2);
    s2 += __shfl_xor_sync(0xffffffffu, s2, 2);
    s1 += __shfl_xor_sync(0xffffffffu, s1, 4);
    s2 += __shfl_xor_sync(0xffffffffu, s2, 4);
    float mean = s1 * (1.f / 128.f);
    float var  = s2 * (1.f / 128.f) - mean * mean;
    float rstd = rsqrtf(var + 1e-5f);

    const float4* gp = (const float4*)lng + fb;
    const float4* bp = (const float4*)lnb + fb;
    float4 y4[4];
    #pragma unroll
    for (int j = 0; j < 4; ++j) {
        float4 gg = gp[j], bb = bp[j];
        y4[j].x = fmaxf((v4[j].x - mean) * rstd * gg.x + bb.x, 0.f);
        y4[j].y = fmaxf((v4[j].y - mean) * rstd * gg.y + bb.y, 0.f);
        y4[j].z = fmaxf((v4[j].z - mean) * rstd * gg.z + bb.z, 0.f);
        y4[j].w = fmaxf((v4[j].w - mean) * rstd * gg.w + bb.w, 0.f);
    }

    if (WRITE_H) {
        if (g == 0) {
            float4* op = (float4*)outh + (size_t)n * 32 + fb;
            #pragma unroll
            for (int j = 0; j < 4; ++j) op[j] = y4[j];
        }
    } else {
        const float4* wp = (const float4*)headW + fb;
        float pp = 0.f;
        #pragma unroll
        for (int j = 0; j < 4; ++j) {
            float4 w4 = wp[j];
            pp = fmaf(y4[j].x, w4.x, pp);
            pp = fmaf(y4[j].y, w4.y, pp);
            pp = fmaf(y4[j].z, w4.z, pp);
            pp = fmaf(y4[j].w, w4.w, pp);
        }
        pp += __shfl_xor_sync(0xffffffffu, pp, 1);
        pp += __shfl_xor_sync(0xffffffffu, pp, 2);
        pp += __shfl_xor_sync(0xffffffffu, pp, 4);
        if (lane == 0) outsc[n] = pp + headb[0];
    }
}

// ---------------- launch ----------------
extern "C" void kernel_launch(void* const* d_in, const int* in_sizes, int n_in,
                              void* d_out, int out_size) {
    const float* x     = (const float*)d_in[0];
    const int*   ei    = (const int*)d_in[1];
    const float* W_in  = (const float*)d_in[2];
    const float* b_in  = (const float*)d_in[3];
    const float* c1_Wl = (const float*)d_in[4];
    const float* c1_bl = (const float*)d_in[5];
    const float* c1_Wr = (const float*)d_in[6];
    const float* c1_br = (const float*)d_in[7];
    const float* c1_att= (const float*)d_in[8];
    const float* c1_b  = (const float*)d_in[9];
    const float* ln1_g = (const float*)d_in[10];
    const float* ln1_b = (const float*)d_in[11];
    const float* a_Wl  = (const float*)d_in[12];
    const float* a_bl  = (const float*)d_in[13];
    const float* a_Wr  = (const float*)d_in[14];
    const float* a_br  = (const float*)d_in[15];
    const float* a_att = (const float*)d_in[16];
    const float* a_b   = (const float*)d_in[17];
    const float* aln_g = (const float*)d_in[18];
    const float* aln_b = (const float*)d_in[19];
    const float* ah_W  = (const float*)d_in[20];
    const float* ah_b  = (const float*)d_in[21];
    const float* k_Wl  = (const float*)d_in[22];
    const float* k_bl  = (const float*)d_in[23];
    const float* k_Wr  = (const float*)d_in[24];
    const float* k_br  = (const float*)d_in[25];
    const float* k_att = (const float*)d_in[26];
    const float* k_b   = (const float*)d_in[27];
    const float* kln_g = (const float*)d_in[28];
    const float* kln_b = (const float*)d_in[29];
    const float* kh_W  = (const float*)d_in[30];
    const float* kh_b  = (const float*)d_in[31];

    int N = in_sizes[0] / 128;
    int E = in_sizes[1] / 2;
    float* out = (float*)d_out;

    float *h1, *h2, *xlxr;
    __nv_bfloat16 *wthi, *wtlo;
    cudaGetSymbolAddress((void**)&h1, g_h1);
    cudaGetSymbolAddress((void**)&h2, g_h2);
    cudaGetSymbolAddress((void**)&xlxr, g_xlxr);
    cudaGetSymbolAddress((void**)&wthi, g_wthi);
    cudaGetSymbolAddress((void**)&wtlo, g_wtlo);

    cudaFuncSetAttribute(gemm_mma_k, cudaFuncAttributeMaxDynamicSharedMemorySize, GMM_SMEM);

    // --- CSR build (dst-major, self-loops included) ---
    init_cnt_k<<<(N + 255) / 256, 256>>>(N);
    count_k<<<(E + 255) / 256, 256>>>(ei + E, E);
    scan2_k<<<1, 1024>>>(N);
    scatter_k<<<(E + N + 255) / 256, 256>>>(ei, ei + E, E, N);

    // --- all weight transposes + hi/lo conversion in one launch ---
    conv_all_k<<<(16384 + 6 * 65536 + 255) / 256, 256>>>(
        W_in, c1_Wl, c1_Wr, a_Wl, a_Wr, k_Wl, k_Wr, wthi, wtlo);

    int gm = (N + 127) / 128;
    int gg = (N + 7) / 8;

    // --- input layer: h1 = relu(x @ W_in + b_in) ---
    gemm_mma_k<<<dim3(gm, 1), 256, GMM_SMEM>>>(x, N,
        wthi + (size_t)0 * 128, wtlo + (size_t)0 * 128, b_in, h1, 128, 0, 1);

    // --- GAT layer 1 ---
    gemm_mma_k<<<dim3(gm, 4), 256, GMM_SMEM>>>(h1, N,
        wthi + (size_t)128 * 128, wtlo + (size_t)128 * 128, c1_bl, xlxr, 1024, 0, 0);
    gemm_mma_k<<<dim3(gm, 4), 256, GMM_SMEM>>>(h1, N,
        wthi + (size_t)640 * 128, wtlo + (size_t)640 * 128, c1_br, xlxr, 1024, 512, 0);
    gat2_k<1><<<gg, 256>>>(xlxr, h1, c1_att, c1_b, ln1_g, ln1_b,
                           (const float*)0, (const float*)0, h2, (float*)0, N);

    // --- actor head ---
    gemm_mma_k<<<dim3(gm, 4), 256, GMM_SMEM>>>(h2, N,
        wthi + (size_t)1152 * 128, wtlo + (size_t)1152 * 128, a_bl, xlxr, 1024, 0, 0);
    gemm_mma_k<<<dim3(gm, 4), 256, GMM_SMEM>>>(h2, N,
        wthi + (size_t)1664 * 128, wtlo + (size_t)1664 * 128, a_br, xlxr, 1024, 512, 0);
    gat2_k<0><<<gg, 256>>>(xlxr, h2, a_att, a_b, aln_g, aln_b,
                           ah_W, ah_b, (float*)0, out, N);

    // --- critic head ---
    gemm_mma_k<<<dim3(gm, 4), 256, GMM_SMEM>>>(h2, N,
        wthi + (size_t)2176 * 128, wtlo + (size_t)2176 * 128, k_bl, xlxr, 1024, 0, 0);
    gemm_mma_k<<<dim3(gm, 4), 256, GMM_SMEM>>>(h2, N,
        wthi + (size_t)2688 * 128, wtlo + (size_t)2688 * 128, k_br, xlxr, 1024, 512, 0);
    gat2_k<0><<<gg, 256>>>(xlxr, h2, k_att, k_b, kln_g, kln_b,
                           kh_W, kh_b, (float*)0, out + N, N);
}

// round 5
// speedup vs baseline: 1.3377x; 1.0603x over previous
#include <cuda_runtime.h>
#include <cuda_bf16.h>
#include <math_constants.h>
#include <cstdint>

// Problem constants (fixed dataset shapes)
#define NMAX 20000
#define EMAX 320000
#define ETOT (EMAX + NMAX)

// ---------------- device scratch (static allocations only) ----------------
__device__ float g_h1[(size_t)NMAX * 128];
__device__ float g_h2[(size_t)NMAX * 128];
__device__ float g_xlxr[(size_t)NMAX * 1024];   // [N][0:512]=xl, [512:1024]=xr
__device__ int   g_cnt[NMAX];
__device__ int   g_rp[NMAX + 1];
__device__ int   g_cur[NMAX];
__device__ int   g_csrc[ETOT];

// bf16 hi/lo activations
__device__ __nv_bfloat16 g_ahi[(size_t)NMAX * 128];
__device__ __nv_bfloat16 g_alo[(size_t)NMAX * 128];
// transposed bf16 hi/lo weights: rows = 128(W_in) + 6*512 = 3200, each row 128 bf16
#define WT_ROWS 3200
__device__ __nv_bfloat16 g_wthi[(size_t)WT_ROWS * 128];
__device__ __nv_bfloat16 g_wtlo[(size_t)WT_ROWS * 128];
// packed biases, index-matched to wt rows: [0:128)=b_in, then bl||br per layer
__device__ float g_biasc[WT_ROWS];

// ---------------- CSR build ----------------
__global__ void init_cnt_k(int N) {
    int i = blockIdx.x * blockDim.x + threadIdx.x;
    if (i < N) g_cnt[i] = 1;
}
__global__ void count_k(const int* __restrict__ dstv, int E) {
    int i = blockIdx.x * blockDim.x + threadIdx.x;
    if (i < E) atomicAdd(&g_cnt[dstv[i]], 1);
}
__global__ void scan2_k(int N) {
    __shared__ int wsum[32];
    int tid = threadIdx.x;
    int lane = tid & 31, wid = tid >> 5;
    int per = (N + 1023) >> 10;
    int start = tid * per;
    int s = 0;
    for (int i = 0; i < per; ++i) {
        int idx = start + i;
        if (idx < N) s += g_cnt[idx];
    }
    int v = s;
    #pragma unroll
    for (int off = 1; off < 32; off <<= 1) {
        int t = __shfl_up_sync(0xffffffffu, v, off);
        if (lane >= off) v += t;
    }
    if (lane == 31) wsum[wid] = v;
    __syncthreads();
    if (wid == 0) {
        int w = wsum[lane];
        #pragma unroll
        for (int off = 1; off < 32; off <<= 1) {
            int t = __shfl_up_sync(0xffffffffu, w, off);
            if (lane >= off) w += t;
        }
        wsum[lane] = w;
    }
    __syncthreads();
    int excl = v - s + (wid ? wsum[wid - 1] : 0);
    int run = excl;
    for (int i = 0; i < per; ++i) {
        int idx = start + i;
        if (idx < N) {
            int c = g_cnt[idx];
            g_cur[idx] = run;
            run += c;
            g_rp[idx + 1] = run;
        }
    }
    if (tid == 0) g_rp[0] = 0;
}
__global__ void scatter_k(const int* __restrict__ srcv, const int* __restrict__ dstv,
                          int E, int N) {
    int i = blockIdx.x * blockDim.x + threadIdx.x;
    if (i < E) {
        int d = dstv[i];
        int pos = atomicAdd(&g_cur[d], 1);
        g_csrc[pos] = srcv[i];
    } else if (i < E + N) {
        int n = i - E;
        int pos = atomicAdd(&g_cur[n], 1);
        g_csrc[pos] = n;
    }
}

// ---------------- weights transpose + hi/lo + bias pack, ONE launch ----------------
__global__ void conv_all_k(const float* __restrict__ w0, const float* __restrict__ w1,
                           const float* __restrict__ w2, const float* __restrict__ w3,
                           const float* __restrict__ w4, const float* __restrict__ w5,
                           const float* __restrict__ w6,
                           const float* __restrict__ b0, const float* __restrict__ b1,
                           const float* __restrict__ b2, const float* __restrict__ b3,
                           const float* __restrict__ b4, const float* __restrict__ b5,
                           const float* __restrict__ b6) {
    int i = blockIdx.x * blockDim.x + threadIdx.x;
    const int WELEMS = 16384 + 6 * 65536;
    if (i < WELEMS) {
        const float* W; int cols, rowoff, li;
        if (i < 16384) { W = w0; cols = 128; rowoff = 0; li = i; }
        else {
            int s = (i - 16384) >> 16;
            li = (i - 16384) & 65535;
            W = (s == 0) ? w1 : (s == 1) ? w2 : (s == 2) ? w3 : (s == 3) ? w4 : (s == 4) ? w5 : w6;
            cols = 512; rowoff = 128 + s * 512;
        }
        int k = li / cols, n = li % cols;
        float v = W[li];
        __nv_bfloat16 h = __float2bfloat16(v);
        g_wthi[(size_t)(rowoff + n) * 128 + k] = h;
        g_wtlo[(size_t)(rowoff + n) * 128 + k] = __float2bfloat16(v - __bfloat162float(h));
    } else if (i < WELEMS + WT_ROWS) {
        int j = i - WELEMS;
        float v;
        if (j < 128) v = b0[j];
        else {
            int s = (j - 128) >> 9, t = (j - 128) & 511;
            const float* B = (s == 0) ? b1 : (s == 1) ? b2 : (s == 2) ? b3
                           : (s == 3) ? b4 : (s == 4) ? b5 : b6;
            v = B[t];
        }
        g_biasc[j] = v;
    }
}

// ---------------- activation fp32 -> bf16 hi/lo ----------------
__global__ void conv_a_k(const float* __restrict__ src, int n4) {
    int i = blockIdx.x * blockDim.x + threadIdx.x;
    if (i < n4) {
        float4 v = ((const float4*)src)[i];
        __nv_bfloat16 hx = __float2bfloat16(v.x);
        __nv_bfloat16 hy = __float2bfloat16(v.y);
        __nv_bfloat16 hz = __float2bfloat16(v.z);
        __nv_bfloat16 hw = __float2bfloat16(v.w);
        __nv_bfloat16 lx = __float2bfloat16(v.x - __bfloat162float(hx));
        __nv_bfloat16 ly = __float2bfloat16(v.y - __bfloat162float(hy));
        __nv_bfloat16 lz = __float2bfloat16(v.z - __bfloat162float(hz));
        __nv_bfloat16 lw = __float2bfloat16(v.w - __bfloat162float(hw));
        uint32_t h01 = (uint32_t)__bfloat16_as_ushort(hx) | ((uint32_t)__bfloat16_as_ushort(hy) << 16);
        uint32_t h23 = (uint32_t)__bfloat16_as_ushort(hz) | ((uint32_t)__bfloat16_as_ushort(hw) << 16);
        uint32_t l01 = (uint32_t)__bfloat16_as_ushort(lx) | ((uint32_t)__bfloat16_as_ushort(ly) << 16);
        uint32_t l23 = (uint32_t)__bfloat16_as_ushort(lz) | ((uint32_t)__bfloat16_as_ushort(lw) << 16);
        ((uint2*)g_ahi)[i] = make_uint2(h01, h23);
        ((uint2*)g_alo)[i] = make_uint2(l01, l23);
    }
}

// ================= bf16x3 tensor-core GEMM (mma.sync + ldmatrix) =================
#define TSTRIDE 272
#define TILE_BYTES (128 * TSTRIDE)
#define GMM_SMEM (4 * TILE_BYTES)

__device__ __forceinline__ uint32_t smem_u32(const void* p) {
    uint32_t a;
    asm("{ .reg .u64 t; cvta.to.shared.u64 t, %1; cvt.u32.u64 %0, t; }" : "=r"(a) : "l"(p));
    return a;
}

#define LDMX4(r0, r1, r2, r3, addr) \
    asm volatile("ldmatrix.sync.aligned.m8n8.x4.shared.b16 {%0,%1,%2,%3}, [%4];" \
                 : "=r"(r0), "=r"(r1), "=r"(r2), "=r"(r3) : "r"(addr))

#define MMA_BF16(c, a0, a1, a2, a3, b0, b1) \
    asm volatile("mma.sync.aligned.m16n8k16.row.col.f32.bf16.bf16.f32 " \
                 "{%0,%1,%2,%3}, {%4,%5,%6,%7}, {%8,%9}, {%0,%1,%2,%3};" \
                 : "+f"((c)[0]), "+f"((c)[1]), "+f"((c)[2]), "+f"((c)[3]) \
                 : "r"(a0), "r"(a1), "r"(a2), "r"(a3), "r"(b0), "r"(b1))

__global__ void __launch_bounds__(256, 1)
gemm_mma_k(const __nv_bfloat16* __restrict__ Ahi, const __nv_bfloat16* __restrict__ Alo, int M,
           const __nv_bfloat16* __restrict__ Bhi, const __nv_bfloat16* __restrict__ Blo,
           const float* __restrict__ bias,
           float* __restrict__ out, int ldo, int do_relu) {
    extern __shared__ char sm[];
    char* sAhi = sm;
    char* sAlo = sm + TILE_BYTES;
    char* sBhi = sm + 2 * TILE_BYTES;
    char* sBlo = sm + 3 * TILE_BYTES;

    int tid = threadIdx.x;
    int row0 = blockIdx.x * 128;
    int wc0  = blockIdx.y * 128;

    // --- A tiles (bf16, guarded) ---
    #pragma unroll
    for (int it = 0; it < 8; ++it) {
        int idx = it * 256 + tid;
        int row = idx >> 4, c = idx & 15;
        uint4 vh = make_uint4(0u, 0u, 0u, 0u), vl = vh;
        if (row0 + row < M) {
            vh = *(const uint4*)((const char*)(Ahi + (size_t)(row0 + row) * 128) + c * 16);
            vl = *(const uint4*)((const char*)(Alo + (size_t)(row0 + row) * 128) + c * 16);
        }
        *(uint4*)(sAhi + row * TSTRIDE + c * 16) = vh;
        *(uint4*)(sAlo + row * TSTRIDE + c * 16) = vl;
    }
    // --- B tiles ---
    #pragma unroll
    for (int it = 0; it < 8; ++it) {
        int idx = it * 256 + tid;
        int row = idx >> 4, c = idx & 15;
        *(uint4*)(sBhi + row * TSTRIDE + c * 16) =
            *(const uint4*)((const char*)(Bhi + (size_t)(wc0 + row) * 128) + c * 16);
        *(uint4*)(sBlo + row * TSTRIDE + c * 16) =
            *(const uint4*)((const char*)(Blo + (size_t)(wc0 + row) * 128) + c * 16);
    }
    __syncthreads();

    int wid = tid >> 5;
    int lane = tid & 31;
    int warp_m = wid & 3;
    int warp_n = wid >> 2;

    int gq = lane >> 3, l8 = lane & 7;
    int fr_row = (gq & 1) * 8 + l8;
    int fr_col = (gq >> 1) * 16;

    uint32_t aoff[2], boff[4];
    #pragma unroll
    for (int mt = 0; mt < 2; ++mt)
        aoff[mt] = (uint32_t)((warp_m * 32 + mt * 16 + fr_row) * TSTRIDE + fr_col);
    #pragma unroll
    for (int nt2 = 0; nt2 < 4; ++nt2)
        boff[nt2] = (uint32_t)((warp_n * 64 + nt2 * 16 + fr_row) * TSTRIDE + fr_col);

    uint32_t uAhi = smem_u32(sAhi), uAlo = smem_u32(sAlo);
    uint32_t uBhi = smem_u32(sBhi), uBlo = smem_u32(sBlo);

    float c[2][8][4];
    #pragma unroll
    for (int mt = 0; mt < 2; ++mt)
        #pragma unroll
        for (int nt = 0; nt < 8; ++nt)
            #pragma unroll
            for (int q = 0; q < 4; ++q) c[mt][nt][q] = 0.f;

    // merged mainloop: per k-step load hi/lo fragments once, 3 MMA products
    #pragma unroll
    for (int kk = 0; kk < 8; ++kk) {
        uint32_t ah[2][4], al[2][4];
        #pragma unroll
        for (int mt = 0; mt < 2; ++mt) {
            LDMX4(ah[mt][0], ah[mt][1], ah[mt][2], ah[mt][3], uAhi + aoff[mt] + kk * 32);
            LDMX4(al[mt][0], al[mt][1], al[mt][2], al[mt][3], uAlo + aoff[mt] + kk * 32);
        }
        uint32_t bh[4][4], bl[4][4];
        #pragma unroll
        for (int nt2 = 0; nt2 < 4; ++nt2) {
            LDMX4(bh[nt2][0], bh[nt2][1], bh[nt2][2], bh[nt2][3], uBhi + boff[nt2] + kk * 32);
            LDMX4(bl[nt2][0], bl[nt2][1], bl[nt2][2], bl[nt2][3], uBlo + boff[nt2] + kk * 32);
        }
        #pragma unroll
        for (int mt = 0; mt < 2; ++mt)
            #pragma unroll
            for (int nt = 0; nt < 8; ++nt) {
                int nt2 = nt >> 1, odd = nt & 1;
                MMA_BF16(c[mt][nt], ah[mt][0], ah[mt][1], ah[mt][2], ah[mt][3],
                         bh[nt2][odd], bh[nt2][2 + odd]);
                MMA_BF16(c[mt][nt], ah[mt][0], ah[mt][1], ah[mt][2], ah[mt][3],
                         bl[nt2][odd], bl[nt2][2 + odd]);
                MMA_BF16(c[mt][nt], al[mt][0], al[mt][1], al[mt][2], al[mt][3],
                         bh[nt2][odd], bh[nt2][2 + odd]);
            }
    }

    int qr = lane >> 2;
    int qc = (lane & 3) * 2;
    #pragma unroll
    for (int mt = 0; mt < 2; ++mt) {
        int r_lo = row0 + warp_m * 32 + mt * 16 + qr;
        #pragma unroll
        for (int nt = 0; nt < 8; ++nt) {
            int col = wc0 + warp_n * 64 + nt * 8 + qc;
            float2 bv = *(const float2*)(bias + col);
            float2 v0 = make_float2(c[mt][nt][0] + bv.x, c[mt][nt][1] + bv.y);
            float2 v1 = make_float2(c[mt][nt][2] + bv.x, c[mt][nt][3] + bv.y);
            if (do_relu) {
                v0.x = fmaxf(v0.x, 0.f); v0.y = fmaxf(v0.y, 0.f);
                v1.x = fmaxf(v1.x, 0.f); v1.y = fmaxf(v1.y, 0.f);
            }
            if (r_lo < M)
                *(float2*)(out + (size_t)r_lo * ldo + col) = v0;
            if (r_lo + 8 < M)
                *(float2*)(out + (size_t)(r_lo + 8) * ldo + col) = v1;
        }
    }
}

// ================= GATv2: warp/node, 8-lane head groups, 2-edge unroll =================
#define LRD(t, x4, r4, a4) do {                                        \
    float ex = (x4).x + (r4).x; ex = fmaxf(ex, 0.2f * ex); t = fmaf(ex, (a4).x, t); \
    float ey = (x4).y + (r4).y; ey = fmaxf(ey, 0.2f * ey); t = fmaf(ey, (a4).y, t); \
    float ez = (x4).z + (r4).z; ez = fmaxf(ez, 0.2f * ez); t = fmaf(ez, (a4).z, t); \
    float ew = (x4).w + (r4).w; ew = fmaxf(ew, 0.2f * ew); t = fmaf(ew, (a4).w, t); \
} while (0)

template <int WRITE_H>
__global__ void __launch_bounds__(256)
gat2_k(const float* __restrict__ xlxr,
       const float* __restrict__ hres,
       const float* __restrict__ att,
       const float* __restrict__ gatb,
       const float* __restrict__ lng,
       const float* __restrict__ lnb,
       const float* __restrict__ headW,
       const float* __restrict__ headb,
       float* __restrict__ outh,
       float* __restrict__ outsc,
       int N) {
    int n    = (blockIdx.x * blockDim.x + threadIdx.x) >> 5;
    int lane = threadIdx.x & 31;
    if (n >= N) return;
    int g  = lane >> 3;
    int l8 = lane & 7;
    int cb = g * 32 + l8 * 4;

    float4 atv[4], xrv[4];
    const float4* ap = (const float4*)att + cb;
    const float4* xp = (const float4*)(xlxr + (size_t)n * 1024 + 512) + cb;
    #pragma unroll
    for (int j = 0; j < 4; ++j) { atv[j] = ap[j]; xrv[j] = xp[j]; }

    float m = -CUDART_INF_F, d = 0.f;
    float4 acc[4];
    #pragma unroll
    for (int j = 0; j < 4; ++j) acc[j] = make_float4(0.f, 0.f, 0.f, 0.f);

    int e = g_rp[n], end = g_rp[n + 1];
    for (; e + 2 <= end; e += 2) {
        int s0 = g_csrc[e];
        int s1 = g_csrc[e + 1];
        const float4* q0 = (const float4*)(xlxr + (size_t)s0 * 1024) + cb;
        const float4* q1 = (const float4*)(xlxr + (size_t)s1 * 1024) + cb;
        float4 x0[4], x1[4];
        #pragma unroll
        for (int j = 0; j < 4; ++j) x0[j] = q0[j];
        #pragma unroll
        for (int j = 0; j < 4; ++j) x1[j] = q1[j];

        float t0 = 0.f, t1 = 0.f;
        #pragma unroll
        for (int j = 0; j < 4; ++j) { LRD(t0, x0[j], xrv[j], atv[j]); LRD(t1, x1[j], xrv[j], atv[j]); }
        t0 += __shfl_xor_sync(0xffffffffu, t0, 1);
        t1 += __shfl_xor_sync(0xffffffffu, t1, 1);
        t0 += __shfl_xor_sync(0xffffffffu, t0, 2);
        t1 += __shfl_xor_sync(0xffffffffu, t1, 2);
        t0 += __shfl_xor_sync(0xffffffffu, t0, 4);
        t1 += __shfl_xor_sync(0xffffffffu, t1, 4);

        float mn = fmaxf(m, fmaxf(t0, t1));
        float sc = __expf(m - mn);
        float p0 = __expf(t0 - mn);
        float p1 = __expf(t1 - mn);
        d = fmaf(d, sc, p0 + p1);
        #pragma unroll
        for (int j = 0; j < 4; ++j) {
            acc[j].x = fmaf(acc[j].x, sc, fmaf(p0, x0[j].x, p1 * x1[j].x));
            acc[j].y = fmaf(acc[j].y, sc, fmaf(p0, x0[j].y, p1 * x1[j].y));
            acc[j].z = fmaf(acc[j].z, sc, fmaf(p0, x0[j].z, p1 * x1[j].z));
            acc[j].w = fmaf(acc[j].w, sc, fmaf(p0, x0[j].w, p1 * x1[j].w));
        }
        m = mn;
    }
    if (e < end) {
        int s0 = g_csrc[e];
        const float4* q0 = (const float4*)(xlxr + (size_t)s0 * 1024) + cb;
        float4 x0[4];
        #pragma unroll
        for (int j = 0; j < 4; ++j) x0[j] = q0[j];
        float t0 = 0.f;
        #pragma unroll
        for (int j = 0; j < 4; ++j) LRD(t0, x0[j], xrv[j], atv[j]);
        t0 += __shfl_xor_sync(0xffffffffu, t0, 1);
        t0 += __shfl_xor_sync(0xffffffffu, t0, 2);
        t0 += __shfl_xor_sync(0xffffffffu, t0, 4);
        float mn = fmaxf(m, t0);
        float sc = __expf(m - mn);
        float p0 = __expf(t0 - mn);
        d = fmaf(d, sc, p0);
        #pragma unroll
        for (int j = 0; j < 4; ++j) {
            acc[j].x = fmaf(acc[j].x, sc, p0 * x0[j].x);
            acc[j].y = fmaf(acc[j].y, sc, p0 * x0[j].y);
            acc[j].z = fmaf(acc[j].z, sc, p0 * x0[j].z);
            acc[j].w = fmaf(acc[j].w, sc, p0 * x0[j].w);
        }
        m = mn;
    }

    float inv = 0.25f / d;
    float* a = (float*)acc;
    #pragma unroll
    for (int i = 0; i < 16; ++i) {
        float v = a[i] * inv;
        v += __shfl_xor_sync(0xffffffffu, v, 8);
        v += __shfl_xor_sync(0xffffffffu, v, 16);
        a[i] = v;
    }

    int fb = l8 * 4;
    const float4* gbp = (const float4*)gatb + fb;
    const float4* hrp = (const float4*)(hres + (size_t)n * 128) + fb;
    float4 v4[4];
    float s1 = 0.f, s2 = 0.f;
    #pragma unroll
    for (int j = 0; j < 4; ++j) {
        float4 gb = gbp[j], hr = hrp[j];
        v4[j].x = acc[j].x + gb.x + hr.x;
        v4[j].y = acc[j].y + gb.y + hr.y;
        v4[j].z = acc[j].z + gb.z + hr.z;
        v4[j].w = acc[j].w + gb.w + hr.w;
        s1 += v4[j].x + v4[j].y + v4[j].z + v4[j].w;
        s2 += v4[j].x * v4[j].x + v4[j].y * v4[j].y + v4[j].z * v4[j].z + v4[j].w * v4[j].w;
    }
    s1 += __shfl_xor_sync(0xffffffffu, s1, 1);
    s2 += __shfl_xor_sync(0xffffffffu, s2, 1);
    s1 += __shfl_xor_sync(0xffffffffu, s1, 2);
    s2 += __shfl_xor_sync(0xffffffffu, s2, 2);
    s1 += __shfl_xor_sync(0xffffffffu, s1, 4);
    s2 += __shfl_xor_sync(0xffffffffu, s2, 4);
    float mean = s1 * (1.f / 128.f);
    float var  = s2 * (1.f / 128.f) - mean * mean;
    float rstd = rsqrtf(var + 1e-5f);

    const float4* gp = (const float4*)lng + fb;
    const float4* bp = (const float4*)lnb + fb;
    float4 y4[4];
    #pragma unroll
    for (int j = 0; j < 4; ++j) {
        float4 gg = gp[j], bb = bp[j];
        y4[j].x = fmaxf((v4[j].x - mean) * rstd * gg.x + bb.x, 0.f);
        y4[j].y = fmaxf((v4[j].y - mean) * rstd * gg.y + bb.y, 0.f);
        y4[j].z = fmaxf((v4[j].z - mean) * rstd * gg.z + bb.z, 0.f);
        y4[j].w = fmaxf((v4[j].w - mean) * rstd * gg.w + bb.w, 0.f);
    }

    if (WRITE_H) {
        if (g == 0) {
            float4* op = (float4*)outh + (size_t)n * 32 + fb;
            #pragma unroll
            for (int j = 0; j < 4; ++j) op[j] = y4[j];
        }
    } else {
        const float4* wp = (const float4*)headW + fb;
        float pp = 0.f;
        #pragma unroll
        for (int j = 0; j < 4; ++j) {
            float4 w4 = wp[j];
            pp = fmaf(y4[j].x, w4.x, pp);
            pp = fmaf(y4[j].y, w4.y, pp);
            pp = fmaf(y4[j].z, w4.z, pp);
            pp = fmaf(y4[j].w, w4.w, pp);
        }
        pp += __shfl_xor_sync(0xffffffffu, pp, 1);
        pp += __shfl_xor_sync(0xffffffffu, pp, 2);
        pp += __shfl_xor_sync(0xffffffffu, pp, 4);
        if (lane == 0) outsc[n] = pp + headb[0];
    }
}

// ---------------- launch ----------------
extern "C" void kernel_launch(void* const* d_in, const int* in_sizes, int n_in,
                              void* d_out, int out_size) {
    const float* x     = (const float*)d_in[0];
    const int*   ei    = (const int*)d_in[1];
    const float* W_in  = (const float*)d_in[2];
    const float* b_in  = (const float*)d_in[3];
    const float* c1_Wl = (const float*)d_in[4];
    const float* c1_bl = (const float*)d_in[5];
    const float* c1_Wr = (const float*)d_in[6];
    const float* c1_br = (const float*)d_in[7];
    const float* c1_att= (const float*)d_in[8];
    const float* c1_b  = (const float*)d_in[9];
    const float* ln1_g = (const float*)d_in[10];
    const float* ln1_b = (const float*)d_in[11];
    const float* a_Wl  = (const float*)d_in[12];
    const float* a_bl  = (const float*)d_in[13];
    const float* a_Wr  = (const float*)d_in[14];
    const float* a_br  = (const float*)d_in[15];
    const float* a_att = (const float*)d_in[16];
    const float* a_b   = (const float*)d_in[17];
    const float* aln_g = (const float*)d_in[18];
    const float* aln_b = (const float*)d_in[19];
    const float* ah_W  = (const float*)d_in[20];
    const float* ah_b  = (const float*)d_in[21];
    const float* k_Wl  = (const float*)d_in[22];
    const float* k_bl  = (const float*)d_in[23];
    const float* k_Wr  = (const float*)d_in[24];
    const float* k_br  = (const float*)d_in[25];
    const float* k_att = (const float*)d_in[26];
    const float* k_b   = (const float*)d_in[27];
    const float* kln_g = (const float*)d_in[28];
    const float* kln_b = (const float*)d_in[29];
    const float* kh_W  = (const float*)d_in[30];
    const float* kh_b  = (const float*)d_in[31];

    int N = in_sizes[0] / 128;
    int E = in_sizes[1] / 2;
    float* out = (float*)d_out;

    float *h1, *h2, *xlxr, *biasc;
    __nv_bfloat16 *ahi, *alo, *wthi, *wtlo;
    cudaGetSymbolAddress((void**)&h1, g_h1);
    cudaGetSymbolAddress((void**)&h2, g_h2);
    cudaGetSymbolAddress((void**)&xlxr, g_xlxr);
    cudaGetSymbolAddress((void**)&biasc, g_biasc);
    cudaGetSymbolAddress((void**)&ahi, g_ahi);
    cudaGetSymbolAddress((void**)&alo, g_alo);
    cudaGetSymbolAddress((void**)&wthi, g_wthi);
    cudaGetSymbolAddress((void**)&wtlo, g_wtlo);

    cudaFuncSetAttribute(gemm_mma_k, cudaFuncAttributeMaxDynamicSharedMemorySize, GMM_SMEM);

    int gm = (N + 127) / 128;
    int gg = (N + 7) / 8;
    int gc = (N * 32 + 255) / 256;   // conv_a handles float4 chunks

    // Order chosen so the ncu window (harness+4th launch) captures gemm_mma_k.
    init_cnt_k<<<(N + 255) / 256, 256>>>(N);                               // 1
    conv_all_k<<<(16384 + 6 * 65536 + WT_ROWS + 255) / 256, 256>>>(        // 2
        W_in, c1_Wl, c1_Wr, a_Wl, a_Wr, k_Wl, k_Wr,
        b_in, c1_bl, c1_br, a_bl, a_br, k_bl, k_br);
    conv_a_k<<<gc, 256>>>(x, N * 32);                                      // 3
    gemm_mma_k<<<dim3(gm, 1), 256, GMM_SMEM>>>(ahi, alo, N,                // 4 <- profiled
        wthi, wtlo, biasc, h1, 128, 1);

    count_k<<<(E + 255) / 256, 256>>>(ei + E, E);                          // 5
    scan2_k<<<1, 1024>>>(N);                                               // 6
    scatter_k<<<(E + N + 255) / 256, 256>>>(ei, ei + E, E, N);             // 7

    // --- GAT layer 1: one merged Wl||Wr GEMM (y=8 covers 1024 cols) ---
    conv_a_k<<<gc, 256>>>(h1, N * 32);                                     // 8
    gemm_mma_k<<<dim3(gm, 8), 256, GMM_SMEM>>>(ahi, alo, N,                // 9
        wthi + (size_t)128 * 128, wtlo + (size_t)128 * 128, biasc + 128, xlxr, 1024, 0);
    gat2_k<1><<<gg, 256>>>(xlxr, h1, c1_att, c1_b, ln1_g, ln1_b,           // 10
                           (const float*)0, (const float*)0, h2, (float*)0, N);

    // --- actor head ---
    conv_a_k<<<gc, 256>>>(h2, N * 32);                                     // 11
    gemm_mma_k<<<dim3(gm, 8), 256, GMM_SMEM>>>(ahi, alo, N,                // 12
        wthi + (size_t)1152 * 128, wtlo + (size_t)1152 * 128, biasc + 1152, xlxr, 1024, 0);
    gat2_k<0><<<gg, 256>>>(xlxr, h2, a_att, a_b, aln_g, aln_b,             // 13
                           ah_W, ah_b, (float*)0, out, N);

    // --- critic head ---
    gemm_mma_k<<<dim3(gm, 8), 256, GMM_SMEM>>>(ahi, alo, N,                // 14
        wthi + (size_t)2176 * 128, wtlo + (size_t)2176 * 128, biasc + 2176, xlxr, 1024, 0);
    gat2_k<0><<<gg, 256>>>(xlxr, h2, k_att, k_b, kln_g, kln_b,             // 15
                           kh_W, kh_b, (float*)0, out + N, N);
}

// round 6
// speedup vs baseline: 1.4174x; 1.0596x over previous
#include <cuda_runtime.h>
#include <cuda_bf16.h>
#include <math_constants.h>
#include <cstdint>

// Problem constants (fixed dataset shapes)
#define NMAX 20000
#define EMAX 320000
#define ETOT (EMAX + NMAX)

// ---------------- device scratch (static allocations only) ----------------
__device__ float g_h1[(size_t)NMAX * 128];
__device__ float g_h2[(size_t)NMAX * 128];
__device__ float g_xlxr[(size_t)NMAX * 1024];    // layer1 & actor: [xl(512) | xr(512)]
__device__ float g_xlxr2[(size_t)NMAX * 1024];   // critic
__device__ int   g_cnt[NMAX];
__device__ int   g_rp[NMAX + 1];
__device__ int   g_cur[NMAX];
__device__ int   g_csrc[ETOT];

// bf16 hi/lo activations
__device__ __nv_bfloat16 g_ahi[(size_t)NMAX * 128];
__device__ __nv_bfloat16 g_alo[(size_t)NMAX * 128];
// transposed bf16 hi/lo weights: rows = 128(W_in) + 6*512 = 3200, each row 128 bf16
#define WT_ROWS 3200
__device__ __nv_bfloat16 g_wthi[(size_t)WT_ROWS * 128];
__device__ __nv_bfloat16 g_wtlo[(size_t)WT_ROWS * 128];
// packed biases, index-matched to wt rows
__device__ float g_biasc[WT_ROWS];

// ---------------- CSR build ----------------
__global__ void init_cnt_k(int N) {
    int i = blockIdx.x * blockDim.x + threadIdx.x;
    if (i < N) g_cnt[i] = 1;
}
__global__ void count_k(const int* __restrict__ dstv, int E) {
    int i = blockIdx.x * blockDim.x + threadIdx.x;
    if (i < E) atomicAdd(&g_cnt[dstv[i]], 1);
}
__global__ void scan2_k(int N) {
    __shared__ int wsum[32];
    int tid = threadIdx.x;
    int lane = tid & 31, wid = tid >> 5;
    int per = (N + 1023) >> 10;
    int start = tid * per;
    int s = 0;
    for (int i = 0; i < per; ++i) {
        int idx = start + i;
        if (idx < N) s += g_cnt[idx];
    }
    int v = s;
    #pragma unroll
    for (int off = 1; off < 32; off <<= 1) {
        int t = __shfl_up_sync(0xffffffffu, v, off);
        if (lane >= off) v += t;
    }
    if (lane == 31) wsum[wid] = v;
    __syncthreads();
    if (wid == 0) {
        int w = wsum[lane];
        #pragma unroll
        for (int off = 1; off < 32; off <<= 1) {
            int t = __shfl_up_sync(0xffffffffu, w, off);
            if (lane >= off) w += t;
        }
        wsum[lane] = w;
    }
    __syncthreads();
    int excl = v - s + (wid ? wsum[wid - 1] : 0);
    int run = excl;
    for (int i = 0; i < per; ++i) {
        int idx = start + i;
        if (idx < N) {
            int c = g_cnt[idx];
            g_cur[idx] = run;
            run += c;
            g_rp[idx + 1] = run;
        }
    }
    if (tid == 0) g_rp[0] = 0;
}
__global__ void scatter_k(const int* __restrict__ srcv, const int* __restrict__ dstv,
                          int E, int N) {
    int i = blockIdx.x * blockDim.x + threadIdx.x;
    if (i < E) {
        int d = dstv[i];
        int pos = atomicAdd(&g_cur[d], 1);
        g_csrc[pos] = srcv[i];
    } else if (i < E + N) {
        int n = i - E;
        int pos = atomicAdd(&g_cur[n], 1);
        g_csrc[pos] = n;
    }
}

// ---------------- weights transpose + hi/lo + bias pack, ONE launch ----------------
__global__ void conv_all_k(const float* __restrict__ w0, const float* __restrict__ w1,
                           const float* __restrict__ w2, const float* __restrict__ w3,
                           const float* __restrict__ w4, const float* __restrict__ w5,
                           const float* __restrict__ w6,
                           const float* __restrict__ b0, const float* __restrict__ b1,
                           const float* __restrict__ b2, const float* __restrict__ b3,
                           const float* __restrict__ b4, const float* __restrict__ b5,
                           const float* __restrict__ b6) {
    int i = blockIdx.x * blockDim.x + threadIdx.x;
    const int WELEMS = 16384 + 6 * 65536;
    if (i < WELEMS) {
        const float* W; int cols, rowoff, li;
        if (i < 16384) { W = w0; cols = 128; rowoff = 0; li = i; }
        else {
            int s = (i - 16384) >> 16;
            li = (i - 16384) & 65535;
            W = (s == 0) ? w1 : (s == 1) ? w2 : (s == 2) ? w3 : (s == 3) ? w4 : (s == 4) ? w5 : w6;
            cols = 512; rowoff = 128 + s * 512;
        }
        int k = li / cols, n = li % cols;
        float v = W[li];
        __nv_bfloat16 h = __float2bfloat16(v);
        g_wthi[(size_t)(rowoff + n) * 128 + k] = h;
        g_wtlo[(size_t)(rowoff + n) * 128 + k] = __float2bfloat16(v - __bfloat162float(h));
    } else if (i < WELEMS + WT_ROWS) {
        int j = i - WELEMS;
        float v;
        if (j < 128) v = b0[j];
        else {
            int s = (j - 128) >> 9, t = (j - 128) & 511;
            const float* B = (s == 0) ? b1 : (s == 1) ? b2 : (s == 2) ? b3
                           : (s == 3) ? b4 : (s == 4) ? b5 : b6;
            v = B[t];
        }
        g_biasc[j] = v;
    }
}

// ---------------- activation fp32 -> bf16 hi/lo ----------------
__global__ void conv_a_k(const float* __restrict__ src, int n4) {
    int i = blockIdx.x * blockDim.x + threadIdx.x;
    if (i < n4) {
        float4 v = ((const float4*)src)[i];
        __nv_bfloat16 hx = __float2bfloat16(v.x);
        __nv_bfloat16 hy = __float2bfloat16(v.y);
        __nv_bfloat16 hz = __float2bfloat16(v.z);
        __nv_bfloat16 hw = __float2bfloat16(v.w);
        __nv_bfloat16 lx = __float2bfloat16(v.x - __bfloat162float(hx));
        __nv_bfloat16 ly = __float2bfloat16(v.y - __bfloat162float(hy));
        __nv_bfloat16 lz = __float2bfloat16(v.z - __bfloat162float(hz));
        __nv_bfloat16 lw = __float2bfloat16(v.w - __bfloat162float(hw));
        uint32_t h01 = (uint32_t)__bfloat16_as_ushort(hx) | ((uint32_t)__bfloat16_as_ushort(hy) << 16);
        uint32_t h23 = (uint32_t)__bfloat16_as_ushort(hz) | ((uint32_t)__bfloat16_as_ushort(hw) << 16);
        uint32_t l01 = (uint32_t)__bfloat16_as_ushort(lx) | ((uint32_t)__bfloat16_as_ushort(ly) << 16);
        uint32_t l23 = (uint32_t)__bfloat16_as_ushort(lz) | ((uint32_t)__bfloat16_as_ushort(lw) << 16);
        ((uint2*)g_ahi)[i] = make_uint2(h01, h23);
        ((uint2*)g_alo)[i] = make_uint2(l01, l23);
    }
}

// ================= bf16x3 tensor-core GEMM: 128x64 tile, 2 CTAs/SM, cp.async =================
#define TSTRIDE 272
#define A_TILE_B (128 * TSTRIDE)   // 34816
#define B_TILE_B (64 * TSTRIDE)    // 17408
#define GMM_SMEM (2 * A_TILE_B + 2 * B_TILE_B)   // 104448

__device__ __forceinline__ uint32_t smem_u32(const void* p) {
    uint32_t a;
    asm("{ .reg .u64 t; cvta.to.shared.u64 t, %1; cvt.u32.u64 %0, t; }" : "=r"(a) : "l"(p));
    return a;
}

#define CP16(dst, src, sz) \
    asm volatile("cp.async.cg.shared.global [%0], [%1], 16, %2;" \
                 :: "r"(dst), "l"(src), "r"(sz) : "memory")
#define CP_COMMIT() asm volatile("cp.async.commit_group;" ::: "memory")
#define CP_WAIT0()  asm volatile("cp.async.wait_group 0;" ::: "memory")

#define LDMX4(r0, r1, r2, r3, addr) \
    asm volatile("ldmatrix.sync.aligned.m8n8.x4.shared.b16 {%0,%1,%2,%3}, [%4];" \
                 : "=r"(r0), "=r"(r1), "=r"(r2), "=r"(r3) : "r"(addr))

#define MMA_BF16(c, a0, a1, a2, a3, b0, b1) \
    asm volatile("mma.sync.aligned.m16n8k16.row.col.f32.bf16.bf16.f32 " \
                 "{%0,%1,%2,%3}, {%4,%5,%6,%7}, {%8,%9}, {%0,%1,%2,%3};" \
                 : "+f"((c)[0]), "+f"((c)[1]), "+f"((c)[2]), "+f"((c)[3]) \
                 : "r"(a0), "r"(a1), "r"(a2), "r"(a3), "r"(b0), "r"(b1))

__global__ void __launch_bounds__(256, 2)
gemm_mma_k(const __nv_bfloat16* __restrict__ Ahi, const __nv_bfloat16* __restrict__ Alo, int M,
           const __nv_bfloat16* __restrict__ Bhi, const __nv_bfloat16* __restrict__ Blo,
           const float* __restrict__ bias,
           float* __restrict__ out, float* __restrict__ out2, int split,
           int ldo, int do_relu) {
    extern __shared__ char sm[];
    char* sAhi = sm;
    char* sAlo = sm + A_TILE_B;
    char* sBhi = sm + 2 * A_TILE_B;
    char* sBlo = sm + 2 * A_TILE_B + B_TILE_B;

    int tid = threadIdx.x;
    int row0 = blockIdx.x * 128;
    int wc0  = blockIdx.y * 64;          // global output-col base (bias/B index)
    int oc   = wc0;                      // local col base for the output buffer
    if (oc >= split) { out = out2; oc -= split; }

    uint32_t uAhi = smem_u32(sAhi), uAlo = smem_u32(sAlo);
    uint32_t uBhi = smem_u32(sBhi), uBlo = smem_u32(sBlo);

    // --- A tiles via cp.async: 128 rows x 16 chunks, hi+lo ---
    #pragma unroll
    for (int it = 0; it < 8; ++it) {
        int idx = it * 256 + tid;
        int row = idx >> 4, c = idx & 15;
        int grow = row0 + row;
        int ok = grow < M;
        int srow = ok ? grow : (M - 1);
        uint32_t sz = ok ? 16u : 0u;
        CP16(uAhi + row * TSTRIDE + c * 16,
             (const char*)(Ahi + (size_t)srow * 128) + c * 16, sz);
        CP16(uAlo + row * TSTRIDE + c * 16,
             (const char*)(Alo + (size_t)srow * 128) + c * 16, sz);
    }
    // --- B tiles: 64 rows x 16 chunks, hi+lo (always in-range) ---
    #pragma unroll
    for (int it = 0; it < 4; ++it) {
        int idx = it * 256 + tid;
        int row = idx >> 4, c = idx & 15;
        CP16(uBhi + row * TSTRIDE + c * 16,
             (const char*)(Bhi + (size_t)(wc0 + row) * 128) + c * 16, 16u);
        CP16(uBlo + row * TSTRIDE + c * 16,
             (const char*)(Blo + (size_t)(wc0 + row) * 128) + c * 16, 16u);
    }
    CP_COMMIT();
    CP_WAIT0();
    __syncthreads();

    int wid = tid >> 5;
    int lane = tid & 31;
    int m0 = (wid & 3) * 32;      // 4 warps along M
    int n0 = (wid >> 2) * 32;     // 2 warps along N

    int gq = lane >> 3, l8 = lane & 7;
    int fr_row = (gq & 1) * 8 + l8;
    int fr_col = (gq >> 1) * 16;

    uint32_t aoff[2], boff[2];
    #pragma unroll
    for (int mt = 0; mt < 2; ++mt)
        aoff[mt] = (uint32_t)((m0 + mt * 16 + fr_row) * TSTRIDE + fr_col);
    #pragma unroll
    for (int nt2 = 0; nt2 < 2; ++nt2)
        boff[nt2] = (uint32_t)((n0 + nt2 * 16 + fr_row) * TSTRIDE + fr_col);

    float c[2][4][4];
    #pragma unroll
    for (int mt = 0; mt < 2; ++mt)
        #pragma unroll
        for (int nt = 0; nt < 4; ++nt)
            #pragma unroll
            for (int q = 0; q < 4; ++q) c[mt][nt][q] = 0.f;

    #pragma unroll
    for (int kk = 0; kk < 8; ++kk) {
        uint32_t ah[2][4], al[2][4];
        #pragma unroll
        for (int mt = 0; mt < 2; ++mt) {
            LDMX4(ah[mt][0], ah[mt][1], ah[mt][2], ah[mt][3], uAhi + aoff[mt] + kk * 32);
            LDMX4(al[mt][0], al[mt][1], al[mt][2], al[mt][3], uAlo + aoff[mt] + kk * 32);
        }
        uint32_t bh[2][4], bl[2][4];
        #pragma unroll
        for (int nt2 = 0; nt2 < 2; ++nt2) {
            LDMX4(bh[nt2][0], bh[nt2][1], bh[nt2][2], bh[nt2][3], uBhi + boff[nt2] + kk * 32);
            LDMX4(bl[nt2][0], bl[nt2][1], bl[nt2][2], bl[nt2][3], uBlo + boff[nt2] + kk * 32);
        }
        #pragma unroll
        for (int mt = 0; mt < 2; ++mt)
            #pragma unroll
            for (int nt = 0; nt < 4; ++nt) {
                int nt2 = nt >> 1, odd = nt & 1;
                MMA_BF16(c[mt][nt], ah[mt][0], ah[mt][1], ah[mt][2], ah[mt][3],
                         bh[nt2][odd], bh[nt2][2 + odd]);
                MMA_BF16(c[mt][nt], ah[mt][0], ah[mt][1], ah[mt][2], ah[mt][3],
                         bl[nt2][odd], bl[nt2][2 + odd]);
                MMA_BF16(c[mt][nt], al[mt][0], al[mt][1], al[mt][2], al[mt][3],
                         bh[nt2][odd], bh[nt2][2 + odd]);
            }
    }

    int qr = lane >> 2;
    int qc = (lane & 3) * 2;
    #pragma unroll
    for (int mt = 0; mt < 2; ++mt) {
        int r_lo = row0 + m0 + mt * 16 + qr;
        #pragma unroll
        for (int nt = 0; nt < 4; ++nt) {
            int colb = n0 + nt * 8 + qc;
            float2 bv = *(const float2*)(bias + wc0 + colb);
            float2 v0 = make_float2(c[mt][nt][0] + bv.x, c[mt][nt][1] + bv.y);
            float2 v1 = make_float2(c[mt][nt][2] + bv.x, c[mt][nt][3] + bv.y);
            if (do_relu) {
                v0.x = fmaxf(v0.x, 0.f); v0.y = fmaxf(v0.y, 0.f);
                v1.x = fmaxf(v1.x, 0.f); v1.y = fmaxf(v1.y, 0.f);
            }
            if (r_lo < M)
                *(float2*)(out + (size_t)r_lo * ldo + oc + colb) = v0;
            if (r_lo + 8 < M)
                *(float2*)(out + (size_t)(r_lo + 8) * ldo + oc + colb) = v1;
        }
    }
}

// ================= GATv2: warp/node, 8-lane head groups, 2-edge unroll =================
#define LRD(t, x4, r4, a4) do {                                        \
    float ex = (x4).x + (r4).x; ex = fmaxf(ex, 0.2f * ex); t = fmaf(ex, (a4).x, t); \
    float ey = (x4).y + (r4).y; ey = fmaxf(ey, 0.2f * ey); t = fmaf(ey, (a4).y, t); \
    float ez = (x4).z + (r4).z; ez = fmaxf(ez, 0.2f * ez); t = fmaf(ez, (a4).z, t); \
    float ew = (x4).w + (r4).w; ew = fmaxf(ew, 0.2f * ew); t = fmaf(ew, (a4).w, t); \
} while (0)

template <int WRITE_H>
__global__ void __launch_bounds__(256)
gat2_k(const float* __restrict__ xlxr,
       const float* __restrict__ hres,
       const float* __restrict__ att,
       const float* __restrict__ gatb,
       const float* __restrict__ lng,
       const float* __restrict__ lnb,
       const float* __restrict__ headW,
       const float* __restrict__ headb,
       float* __restrict__ outh,
       float* __restrict__ outsc,
       int N) {
    int n    = (blockIdx.x * blockDim.x + threadIdx.x) >> 5;
    int lane = threadIdx.x & 31;
    if (n >= N) return;
    int g  = lane >> 3;
    int l8 = lane & 7;
    int cb = g * 32 + l8 * 4;

    float4 atv[4], xrv[4];
    const float4* ap = (const float4*)att + cb;
    const float4* xp = (const float4*)(xlxr + (size_t)n * 1024 + 512) + cb;
    #pragma unroll
    for (int j = 0; j < 4; ++j) { atv[j] = ap[j]; xrv[j] = xp[j]; }

    float m = -CUDART_INF_F, d = 0.f;
    float4 acc[4];
    #pragma unroll
    for (int j = 0; j < 4; ++j) acc[j] = make_float4(0.f, 0.f, 0.f, 0.f);

    int e = g_rp[n], end = g_rp[n + 1];
    for (; e + 2 <= end; e += 2) {
        int s0 = g_csrc[e];
        int s1 = g_csrc[e + 1];
        const float4* q0 = (const float4*)(xlxr + (size_t)s0 * 1024) + cb;
        const float4* q1 = (const float4*)(xlxr + (size_t)s1 * 1024) + cb;
        float4 x0[4], x1[4];
        #pragma unroll
        for (int j = 0; j < 4; ++j) x0[j] = q0[j];
        #pragma unroll
        for (int j = 0; j < 4; ++j) x1[j] = q1[j];

        float t0 = 0.f, t1 = 0.f;
        #pragma unroll
        for (int j = 0; j < 4; ++j) { LRD(t0, x0[j], xrv[j], atv[j]); LRD(t1, x1[j], xrv[j], atv[j]); }
        t0 += __shfl_xor_sync(0xffffffffu, t0, 1);
        t1 += __shfl_xor_sync(0xffffffffu, t1, 1);
        t0 += __shfl_xor_sync(0xffffffffu, t0, 2);
        t1 += __shfl_xor_sync(0xffffffffu, t1, 2);
        t0 += __shfl_xor_sync(0xffffffffu, t0, 4);
        t1 += __shfl_xor_sync(0xffffffffu, t1, 4);

        float mn = fmaxf(m, fmaxf(t0, t1));
        float sc = __expf(m - mn);
        float p0 = __expf(t0 - mn);
        float p1 = __expf(t1 - mn);
        d = fmaf(d, sc, p0 + p1);
        #pragma unroll
        for (int j = 0; j < 4; ++j) {
            acc[j].x = fmaf(acc[j].x, sc, fmaf(p0, x0[j].x, p1 * x1[j].x));
            acc[j].y = fmaf(acc[j].y, sc, fmaf(p0, x0[j].y, p1 * x1[j].y));
            acc[j].z = fmaf(acc[j].z, sc, fmaf(p0, x0[j].z, p1 * x1[j].z));
            acc[j].w = fmaf(acc[j].w, sc, fmaf(p0, x0[j].w, p1 * x1[j].w));
        }
        m = mn;
    }
    if (e < end) {
        int s0 = g_csrc[e];
        const float4* q0 = (const float4*)(xlxr + (size_t)s0 * 1024) + cb;
        float4 x0[4];
        #pragma unroll
        for (int j = 0; j < 4; ++j) x0[j] = q0[j];
        float t0 = 0.f;
        #pragma unroll
        for (int j = 0; j < 4; ++j) LRD(t0, x0[j], xrv[j], atv[j]);
        t0 += __shfl_xor_sync(0xffffffffu, t0, 1);
        t0 += __shfl_xor_sync(0xffffffffu, t0, 2);
        t0 += __shfl_xor_sync(0xffffffffu, t0, 4);
        float mn = fmaxf(m, t0);
        float sc = __expf(m - mn);
        float p0 = __expf(t0 - mn);
        d = fmaf(d, sc, p0);
        #pragma unroll
        for (int j = 0; j < 4; ++j) {
            acc[j].x = fmaf(acc[j].x, sc, p0 * x0[j].x);
            acc[j].y = fmaf(acc[j].y, sc, p0 * x0[j].y);
            acc[j].z = fmaf(acc[j].z, sc, p0 * x0[j].z);
            acc[j].w = fmaf(acc[j].w, sc, p0 * x0[j].w);
        }
        m = mn;
    }

    float inv = 0.25f / d;
    float* a = (float*)acc;
    #pragma unroll
    for (int i = 0; i < 16; ++i) {
        float v = a[i] * inv;
        v += __shfl_xor_sync(0xffffffffu, v, 8);
        v += __shfl_xor_sync(0xffffffffu, v, 16);
        a[i] = v;
    }

    int fb = l8 * 4;
    const float4* gbp = (const float4*)gatb + fb;
    const float4* hrp = (const float4*)(hres + (size_t)n * 128) + fb;
    float4 v4[4];
    float s1 = 0.f, s2 = 0.f;
    #pragma unroll
    for (int j = 0; j < 4; ++j) {
        float4 gb = gbp[j], hr = hrp[j];
        v4[j].x = acc[j].x + gb.x + hr.x;
        v4[j].y = acc[j].y + gb.y + hr.y;
        v4[j].z = acc[j].z + gb.z + hr.z;
        v4[j].w = acc[j].w + gb.w + hr.w;
        s1 += v4[j].x + v4[j].y + v4[j].z + v4[j].w;
        s2 += v4[j].x * v4[j].x + v4[j].y * v4[j].y + v4[j].z * v4[j].z + v4[j].w * v4[j].w;
    }
    s1 += __shfl_xor_sync(0xffffffffu, s1, 1);
    s2 += __shfl_xor_sync(0xffffffffu, s2, 1);
    s1 += __shfl_xor_sync(0xffffffffu, s1, 2);
    s2 += __shfl_xor_sync(0xffffffffu, s2, 2);
    s1 += __shfl_xor_sync(0xffffffffu, s1, 4);
    s2 += __shfl_xor_sync(0xffffffffu, s2, 4);
    float mean = s1 * (1.f / 128.f);
    float var  = s2 * (1.f / 128.f) - mean * mean;
    float rstd = rsqrtf(var + 1e-5f);

    const float4* gp = (const float4*)lng + fb;
    const float4* bp = (const float4*)lnb + fb;
    float4 y4[4];
    #pragma unroll
    for (int j = 0; j < 4; ++j) {
        float4 gg = gp[j], bb = bp[j];
        y4[j].x = fmaxf((v4[j].x - mean) * rstd * gg.x + bb.x, 0.f);
        y4[j].y = fmaxf((v4[j].y - mean) * rstd * gg.y + bb.y, 0.f);
        y4[j].z = fmaxf((v4[j].z - mean) * rstd * gg.z + bb.z, 0.f);
        y4[j].w = fmaxf((v4[j].w - mean) * rstd * gg.w + bb.w, 0.f);
    }

    if (WRITE_H) {
        if (g == 0) {
            float4* op = (float4*)outh + (size_t)n * 32 + fb;
            #pragma unroll
            for (int j = 0; j < 4; ++j) op[j] = y4[j];
        }
    } else {
        const float4* wp = (const float4*)headW + fb;
        float pp = 0.f;
        #pragma unroll
        for (int j = 0; j < 4; ++j) {
            float4 w4 = wp[j];
            pp = fmaf(y4[j].x, w4.x, pp);
            pp = fmaf(y4[j].y, w4.y, pp);
            pp = fmaf(y4[j].z, w4.z, pp);
            pp = fmaf(y4[j].w, w4.w, pp);
        }
        pp += __shfl_xor_sync(0xffffffffu, pp, 1);
        pp += __shfl_xor_sync(0xffffffffu, pp, 2);
        pp += __shfl_xor_sync(0xffffffffu, pp, 4);
        if (lane == 0) outsc[n] = pp + headb[0];
    }
}

// ---------------- launch ----------------
extern "C" void kernel_launch(void* const* d_in, const int* in_sizes, int n_in,
                              void* d_out, int out_size) {
    const float* x     = (const float*)d_in[0];
    const int*   ei    = (const int*)d_in[1];
    const float* W_in  = (const float*)d_in[2];
    const float* b_in  = (const float*)d_in[3];
    const float* c1_Wl = (const float*)d_in[4];
    const float* c1_bl = (const float*)d_in[5];
    const float* c1_Wr = (const float*)d_in[6];
    const float* c1_br = (const float*)d_in[7];
    const float* c1_att= (const float*)d_in[8];
    const float* c1_b  = (const float*)d_in[9];
    const float* ln1_g = (const float*)d_in[10];
    const float* ln1_b = (const float*)d_in[11];
    const float* a_Wl  = (const float*)d_in[12];
    const float* a_bl  = (const float*)d_in[13];
    const float* a_Wr  = (const float*)d_in[14];
    const float* a_br  = (const float*)d_in[15];
    const float* a_att = (const float*)d_in[16];
    const float* a_b   = (const float*)d_in[17];
    const float* aln_g = (const float*)d_in[18];
    const float* aln_b = (const float*)d_in[19];
    const float* ah_W  = (const float*)d_in[20];
    const float* ah_b  = (const float*)d_in[21];
    const float* k_Wl  = (const float*)d_in[22];
    const float* k_bl  = (const float*)d_in[23];
    const float* k_Wr  = (const float*)d_in[24];
    const float* k_br  = (const float*)d_in[25];
    const float* k_att = (const float*)d_in[26];
    const float* k_b   = (const float*)d_in[27];
    const float* kln_g = (const float*)d_in[28];
    const float* kln_b = (const float*)d_in[29];
    const float* kh_W  = (const float*)d_in[30];
    const float* kh_b  = (const float*)d_in[31];

    int N = in_sizes[0] / 128;
    int E = in_sizes[1] / 2;
    float* out = (float*)d_out;

    float *h1, *h2, *xlxr, *xlxr2, *biasc;
    __nv_bfloat16 *ahi, *alo, *wthi, *wtlo;
    cudaGetSymbolAddress((void**)&h1, g_h1);
    cudaGetSymbolAddress((void**)&h2, g_h2);
    cudaGetSymbolAddress((void**)&xlxr, g_xlxr);
    cudaGetSymbolAddress((void**)&xlxr2, g_xlxr2);
    cudaGetSymbolAddress((void**)&biasc, g_biasc);
    cudaGetSymbolAddress((void**)&ahi, g_ahi);
    cudaGetSymbolAddress((void**)&alo, g_alo);
    cudaGetSymbolAddress((void**)&wthi, g_wthi);
    cudaGetSymbolAddress((void**)&wtlo, g_wtlo);

    cudaFuncSetAttribute(gemm_mma_k, cudaFuncAttributeMaxDynamicSharedMemorySize, GMM_SMEM);

    int gm = (N + 127) / 128;
    int gg = (N + 7) / 8;
    int gc = (N * 32 + 255) / 256;
    const int NOSPLIT = 1 << 30;

    // Order chosen so the ncu window (harness+4th launch) captures gemm_mma_k.
    init_cnt_k<<<(N + 255) / 256, 256>>>(N);                               // 1
    conv_all_k<<<(16384 + 6 * 65536 + WT_ROWS + 255) / 256, 256>>>(        // 2
        W_in, c1_Wl, c1_Wr, a_Wl, a_Wr, k_Wl, k_Wr,
        b_in, c1_bl, c1_br, a_bl, a_br, k_bl, k_br);
    conv_a_k<<<gc, 256>>>(x, N * 32);                                      // 3
    gemm_mma_k<<<dim3(gm, 2), 256, GMM_SMEM>>>(ahi, alo, N,                // 4 <- profiled
        wthi, wtlo, biasc, h1, (float*)0, NOSPLIT, 128, 1);

    count_k<<<(E + 255) / 256, 256>>>(ei + E, E);                          // 5
    scan2_k<<<1, 1024>>>(N);                                               // 6
    scatter_k<<<(E + N + 255) / 256, 256>>>(ei, ei + E, E, N);             // 7

    // --- GAT layer 1: merged Wl||Wr GEMM (y=16 covers 1024 cols) ---
    conv_a_k<<<gc, 256>>>(h1, N * 32);                                     // 8
    gemm_mma_k<<<dim3(gm, 16), 256, GMM_SMEM>>>(ahi, alo, N,               // 9
        wthi + (size_t)128 * 128, wtlo + (size_t)128 * 128, biasc + 128,
        xlxr, (float*)0, NOSPLIT, 1024, 0);
    gat2_k<1><<<gg, 256>>>(xlxr, h1, c1_att, c1_b, ln1_g, ln1_b,           // 10
                           (const float*)0, (const float*)0, h2, (float*)0, N);

    // --- actor + critic GEMMs merged (y=32 covers 2048 cols; split at 1024) ---
    conv_a_k<<<gc, 256>>>(h2, N * 32);                                     // 11
    gemm_mma_k<<<dim3(gm, 32), 256, GMM_SMEM>>>(ahi, alo, N,               // 12
        wthi + (size_t)1152 * 128, wtlo + (size_t)1152 * 128, biasc + 1152,
        xlxr, xlxr2, 1024, 1024, 0);
    gat2_k<0><<<gg, 256>>>(xlxr, h2, a_att, a_b, aln_g, aln_b,             // 13
                           ah_W, ah_b, (float*)0, out, N);
    gat2_k<0><<<gg, 256>>>(xlxr2, h2, k_att, k_b, kln_g, kln_b,            // 14
                           kh_W, kh_b, (float*)0, out + N, N);
}